// round 1
// baseline (speedup 1.0000x reference)
#include <cuda_runtime.h>
#include <cuda_bf16.h>
#include <cstddef>

// Problem constants
#define S_LEN 2048
#define BATCH 2
#define EMB   1024
#define HEADS 16
#define HDIM  64
#define MROWS (S_LEN * BATCH)      // 4096
#define MLP_H 512
#define SIGD  64
#define KEEP  12                   // NUM_HEADS - INACTIVE

// ---------------- scratch (device globals; no allocation allowed) -------------
__device__ float g_q[MROWS * EMB];
__device__ float g_k[MROWS * EMB];
__device__ float g_v[MROWS * EMB];
__device__ float g_o[MROWS * EMB];
__device__ float g_t1[MROWS * MLP_H];
__device__ float g_mask[MROWS * HEADS];

// ==============================================================================
// GEMM: C[M,N] = act( (A[M,K] @ W[N,K]^T + bias[N]) * scale )
// A and W are both row-major with K contiguous.
// 128x128 block, BK=16, 256 threads, 8x8 register tile per thread.
// ==============================================================================
#define BM 128
#define BN 128
#define BK 16

__global__ __launch_bounds__(256) void gemm_bias_kernel(
    const float* __restrict__ A, const float* __restrict__ W,
    const float* __restrict__ bias, float* __restrict__ C,
    int M, int N, int K, float scale, int relu)
{
    __shared__ float As[BK][BM + 4];   // [k][m], pad to 132
    __shared__ float Bs[BK][BN + 4];   // [k][n]

    const int tid = threadIdx.x;
    const int tx = tid & 15;
    const int ty = tid >> 4;
    const int m0 = blockIdx.y * BM;
    const int n0 = blockIdx.x * BN;

    float acc[8][8];
#pragma unroll
    for (int i = 0; i < 8; ++i)
#pragma unroll
        for (int j = 0; j < 8; ++j) acc[i][j] = 0.f;

    for (int kk = 0; kk < K; kk += BK) {
        // Load A tile: 128 rows x 16 k = 512 float4, 2 per thread (transpose store)
#pragma unroll
        for (int l = 0; l < 2; ++l) {
            int idx = tid + l * 256;
            int row = idx >> 2;
            int kc  = (idx & 3) * 4;
            float4 v = *(const float4*)&A[(size_t)(m0 + row) * K + kk + kc];
            As[kc + 0][row] = v.x; As[kc + 1][row] = v.y;
            As[kc + 2][row] = v.z; As[kc + 3][row] = v.w;
        }
        // Load W tile: 128 rows x 16 k
#pragma unroll
        for (int l = 0; l < 2; ++l) {
            int idx = tid + l * 256;
            int row = idx >> 2;
            int kc  = (idx & 3) * 4;
            float4 v = *(const float4*)&W[(size_t)(n0 + row) * K + kk + kc];
            Bs[kc + 0][row] = v.x; Bs[kc + 1][row] = v.y;
            Bs[kc + 2][row] = v.z; Bs[kc + 3][row] = v.w;
        }
        __syncthreads();

#pragma unroll
        for (int k = 0; k < BK; ++k) {
            float a[8], b[8];
            *(float4*)&a[0] = *(const float4*)&As[k][ty * 8];
            *(float4*)&a[4] = *(const float4*)&As[k][ty * 8 + 4];
            *(float4*)&b[0] = *(const float4*)&Bs[k][tx * 8];
            *(float4*)&b[4] = *(const float4*)&Bs[k][tx * 8 + 4];
#pragma unroll
            for (int i = 0; i < 8; ++i)
#pragma unroll
                for (int j = 0; j < 8; ++j)
                    acc[i][j] = fmaf(a[i], b[j], acc[i][j]);
        }
        __syncthreads();
    }

    // Epilogue
#pragma unroll
    for (int i = 0; i < 8; ++i) {
        int m = m0 + ty * 8 + i;
#pragma unroll
        for (int j = 0; j < 8; j += 4) {
            int n = n0 + tx * 8 + j;
            float4 r;
            r.x = (acc[i][j + 0] + bias[n + 0]) * scale;
            r.y = (acc[i][j + 1] + bias[n + 1]) * scale;
            r.z = (acc[i][j + 2] + bias[n + 2]) * scale;
            r.w = (acc[i][j + 3] + bias[n + 3]) * scale;
            if (relu) {
                r.x = fmaxf(r.x, 0.f); r.y = fmaxf(r.y, 0.f);
                r.z = fmaxf(r.z, 0.f); r.w = fmaxf(r.w, 0.f);
            }
            *(float4*)&C[(size_t)m * N + n] = r;
        }
    }
}

// ==============================================================================
// Mask kernel: per 64 rows, t2 = t1 @ inf2_w^T + b2 (64 cols, K=512),
// scores = t2 @ head_sig^T (16), mask = s >= 12th-largest(s).
// ==============================================================================
__global__ __launch_bounds__(256) void mask_kernel(
    const float* __restrict__ T1,   // (MROWS, 512), relu already applied
    const float* __restrict__ W2,   // (64, 512)
    const float* __restrict__ b2,   // (64)
    const float* __restrict__ HS,   // (16, 64)
    float* __restrict__ maskOut)    // (MROWS, 16)
{
    __shared__ float As[16][68];
    __shared__ float Ws[16][68];
    __shared__ float T2[64][68];
    __shared__ float HSs[16][68];
    __shared__ float Sc[64][16];

    const int tid = threadIdx.x;
    const int tx = tid & 15;
    const int ty = tid >> 4;
    const int m0 = blockIdx.x * 64;

    // load head_sig (16x64 = 256 float4, 1 per thread)
    {
        int hrow = tid >> 4;
        int c4   = (tid & 15) * 4;
        float4 v = *(const float4*)&HS[(size_t)hrow * 64 + c4];
        *(float4*)&HSs[hrow][c4] = v;
    }

    float acc[4][4];
#pragma unroll
    for (int i = 0; i < 4; ++i)
#pragma unroll
        for (int j = 0; j < 4; ++j) acc[i][j] = 0.f;

    const int row = tid >> 2;          // 0..63
    const int kc  = (tid & 3) * 4;

    for (int kk = 0; kk < MLP_H; kk += 16) {
        float4 a = *(const float4*)&T1[(size_t)(m0 + row) * MLP_H + kk + kc];
        As[kc + 0][row] = a.x; As[kc + 1][row] = a.y;
        As[kc + 2][row] = a.z; As[kc + 3][row] = a.w;
        float4 w = *(const float4*)&W2[(size_t)row * MLP_H + kk + kc];
        Ws[kc + 0][row] = w.x; Ws[kc + 1][row] = w.y;
        Ws[kc + 2][row] = w.z; Ws[kc + 3][row] = w.w;
        __syncthreads();
#pragma unroll
        for (int k = 0; k < 16; ++k) {
            float a4[4], b4[4];
            *(float4*)&a4[0] = *(const float4*)&As[k][ty * 4];
            *(float4*)&b4[0] = *(const float4*)&Ws[k][tx * 4];
#pragma unroll
            for (int i = 0; i < 4; ++i)
#pragma unroll
                for (int j = 0; j < 4; ++j)
                    acc[i][j] = fmaf(a4[i], b4[j], acc[i][j]);
        }
        __syncthreads();
    }

    // t2 with bias into smem
#pragma unroll
    for (int i = 0; i < 4; ++i)
#pragma unroll
        for (int j = 0; j < 4; ++j)
            T2[ty * 4 + i][tx * 4 + j] = acc[i][j] + b2[tx * 4 + j];
    __syncthreads();

    // scores: thread t computes row r = t/4, heads hg..hg+3
    {
        int r  = tid >> 2;
        int hg = (tid & 3) * 4;
        float sc[4] = {0.f, 0.f, 0.f, 0.f};
#pragma unroll 8
        for (int d = 0; d < 64; ++d) {
            float tv = T2[r][d];
            sc[0] = fmaf(tv, HSs[hg + 0][d], sc[0]);
            sc[1] = fmaf(tv, HSs[hg + 1][d], sc[1]);
            sc[2] = fmaf(tv, HSs[hg + 2][d], sc[2]);
            sc[3] = fmaf(tv, HSs[hg + 3][d], sc[3]);
        }
        *(float4*)&Sc[r][hg] = make_float4(sc[0], sc[1], sc[2], sc[3]);
    }
    __syncthreads();

    // per-row top-KEEP threshold + mask write
    if (tid < 64) {
        float vals[16];
#pragma unroll
        for (int h = 0; h < 16; ++h) vals[h] = Sc[tid][h];
        bool used[16];
#pragma unroll
        for (int h = 0; h < 16; ++h) used[h] = false;
        float kth = -1e30f;
        for (int it = 0; it < KEEP; ++it) {
            float mx = -1e30f; int mi = 0;
            for (int h = 0; h < 16; ++h)
                if (!used[h] && vals[h] > mx) { mx = vals[h]; mi = h; }
            used[mi] = true;
            kth = mx;
        }
        for (int h = 0; h < 16; ++h)
            maskOut[(size_t)(m0 + tid) * HEADS + h] = (vals[h] >= kth) ? 1.f : 0.f;
    }
}

// ==============================================================================
// Flash attention: 64 q-rows per CTA, loop over 32 k-tiles of 64, online softmax.
// Q pre-scaled. Epilogue multiplies by head mask and writes (S,B,E) layout.
// Dynamic smem: Qs/Ks ([d][i] transposed), Vs ([j][d]), Ps ([i][j]) — 4*64*68*4 B.
// ==============================================================================
#define FPAD 68
#define FLASH_SMEM (4 * 64 * FPAD * 4)

__global__ __launch_bounds__(256) void flash_kernel(
    const float* __restrict__ Qg, const float* __restrict__ Kg,
    const float* __restrict__ Vg, const float* __restrict__ maskp,
    float* __restrict__ Og)
{
    extern __shared__ float sm[];
    float (*Qs)[FPAD] = (float(*)[FPAD])(sm);
    float (*Ks)[FPAD] = (float(*)[FPAD])(sm + 64 * FPAD);
    float (*Vs)[FPAD] = (float(*)[FPAD])(sm + 2 * 64 * FPAD);
    float (*Ps)[FPAD] = (float(*)[FPAD])(sm + 3 * 64 * FPAD);

    const int tid = threadIdx.x;
    const int tx = tid & 15;
    const int ty = tid >> 4;
    const int qt = blockIdx.x;
    const int h  = blockIdx.y;
    const int b  = blockIdx.z;
    const int s0 = qt * 64;
    const size_t rowstride = (size_t)BATCH * EMB;   // 2048
    const size_t cbase = (size_t)b * EMB + (size_t)h * HDIM;

    // Load Q tile transposed: Qs[d][i]
#pragma unroll
    for (int l = 0; l < 4; ++l) {
        int idx = tid + l * 256;
        int i   = idx >> 4;
        int c4  = (idx & 15) * 4;
        float4 v = *(const float4*)&Qg[(size_t)(s0 + i) * rowstride + cbase + c4];
        Qs[c4 + 0][i] = v.x; Qs[c4 + 1][i] = v.y;
        Qs[c4 + 2][i] = v.z; Qs[c4 + 3][i] = v.w;
    }

    float o[4][4];
    float mrow[4], lrow[4];
#pragma unroll
    for (int ii = 0; ii < 4; ++ii) {
        mrow[ii] = -1e30f; lrow[ii] = 0.f;
#pragma unroll
        for (int dd = 0; dd < 4; ++dd) o[ii][dd] = 0.f;
    }

    for (int kt = 0; kt < S_LEN / 64; ++kt) {
        __syncthreads();   // prior O-update done reading Vs/Ps; also covers Q load on iter 0
        // Load K (transposed) + V (natural)
#pragma unroll
        for (int l = 0; l < 4; ++l) {
            int idx = tid + l * 256;
            int j   = idx >> 4;
            int c4  = (idx & 15) * 4;
            size_t goff = (size_t)(kt * 64 + j) * rowstride + cbase + c4;
            float4 kv = *(const float4*)&Kg[goff];
            Ks[c4 + 0][j] = kv.x; Ks[c4 + 1][j] = kv.y;
            Ks[c4 + 2][j] = kv.z; Ks[c4 + 3][j] = kv.w;
            float4 vv = *(const float4*)&Vg[goff];
            *(float4*)&Vs[j][c4] = vv;
        }
        __syncthreads();

        // S tile: 4x4 per thread
        float sv[4][4];
#pragma unroll
        for (int ii = 0; ii < 4; ++ii)
#pragma unroll
            for (int jj = 0; jj < 4; ++jj) sv[ii][jj] = 0.f;

#pragma unroll 8
        for (int d = 0; d < 64; ++d) {
            float qa[4], ka[4];
            *(float4*)&qa[0] = *(const float4*)&Qs[d][ty * 4];
            *(float4*)&ka[0] = *(const float4*)&Ks[d][tx * 4];
#pragma unroll
            for (int ii = 0; ii < 4; ++ii)
#pragma unroll
                for (int jj = 0; jj < 4; ++jj)
                    sv[ii][jj] = fmaf(qa[ii], ka[jj], sv[ii][jj]);
        }

        // Online softmax (row stats shared across the 16 tx lanes of a half-warp)
#pragma unroll
        for (int ii = 0; ii < 4; ++ii) {
            float tm = fmaxf(fmaxf(sv[ii][0], sv[ii][1]), fmaxf(sv[ii][2], sv[ii][3]));
#pragma unroll
            for (int off = 1; off < 16; off <<= 1)
                tm = fmaxf(tm, __shfl_xor_sync(0xffffffffu, tm, off));
            float mnew  = fmaxf(mrow[ii], tm);
            float alpha = __expf(mrow[ii] - mnew);
            float ls = 0.f;
#pragma unroll
            for (int jj = 0; jj < 4; ++jj) {
                sv[ii][jj] = __expf(sv[ii][jj] - mnew);
                ls += sv[ii][jj];
            }
#pragma unroll
            for (int off = 1; off < 16; off <<= 1)
                ls += __shfl_xor_sync(0xffffffffu, ls, off);
            lrow[ii] = lrow[ii] * alpha + ls;
            mrow[ii] = mnew;
#pragma unroll
            for (int dd = 0; dd < 4; ++dd) o[ii][dd] *= alpha;
            *(float4*)&Ps[ty * 4 + ii][tx * 4] =
                make_float4(sv[ii][0], sv[ii][1], sv[ii][2], sv[ii][3]);
        }
        __syncthreads();

        // O update: o[ii][dd] += sum_j Ps[row][j] * Vs[j][col]
#pragma unroll 4
        for (int j4 = 0; j4 < 16; ++j4) {
            float vv[4][4];
#pragma unroll
            for (int jj = 0; jj < 4; ++jj)
                *(float4*)&vv[jj][0] = *(const float4*)&Vs[j4 * 4 + jj][tx * 4];
#pragma unroll
            for (int ii = 0; ii < 4; ++ii) {
                float p[4];
                *(float4*)&p[0] = *(const float4*)&Ps[ty * 4 + ii][j4 * 4];
#pragma unroll
                for (int jj = 0; jj < 4; ++jj)
#pragma unroll
                    for (int dd = 0; dd < 4; ++dd)
                        o[ii][dd] = fmaf(p[jj], vv[jj][dd], o[ii][dd]);
            }
        }
    }

    // Epilogue: normalize, apply head mask, write (S,B,E)
#pragma unroll
    for (int ii = 0; ii < 4; ++ii) {
        int i = ty * 4 + ii;
        int srow = s0 + i;
        float mval = maskp[((size_t)srow * BATCH + b) * HEADS + h];
        float inv  = mval / lrow[ii];
        float4 r;
        r.x = o[ii][0] * inv; r.y = o[ii][1] * inv;
        r.z = o[ii][2] * inv; r.w = o[ii][3] * inv;
        *(float4*)&Og[(size_t)srow * rowstride + cbase + tx * 4] = r;
    }
}

// ==============================================================================
// launch
// ==============================================================================
extern "C" void kernel_launch(void* const* d_in, const int* in_sizes, int n_in,
                              void* d_out, int out_size)
{
    (void)in_sizes; (void)n_in; (void)out_size;
    const float* query   = (const float*)d_in[0];
    const float* q_w     = (const float*)d_in[1];
    const float* q_b     = (const float*)d_in[2];
    const float* k_w     = (const float*)d_in[3];
    const float* k_b     = (const float*)d_in[4];
    const float* v_w     = (const float*)d_in[5];
    const float* v_b     = (const float*)d_in[6];
    const float* out_w   = (const float*)d_in[7];
    const float* out_b   = (const float*)d_in[8];
    const float* inf1_w  = (const float*)d_in[9];
    const float* inf1_b  = (const float*)d_in[10];
    const float* inf2_w  = (const float*)d_in[11];
    const float* inf2_b  = (const float*)d_in[12];
    const float* head_sig= (const float*)d_in[13];
    float* out = (float*)d_out;

    float* pq;  cudaGetSymbolAddress((void**)&pq,  g_q);
    float* pk;  cudaGetSymbolAddress((void**)&pk,  g_k);
    float* pv;  cudaGetSymbolAddress((void**)&pv,  g_v);
    float* po;  cudaGetSymbolAddress((void**)&po,  g_o);
    float* pt1; cudaGetSymbolAddress((void**)&pt1, g_t1);
    float* pm;  cudaGetSymbolAddress((void**)&pm,  g_mask);

    cudaFuncSetAttribute(flash_kernel,
                         cudaFuncAttributeMaxDynamicSharedMemorySize, FLASH_SMEM);

    const float scaling = 0.125f;   // 64^-0.5

    dim3 gE(EMB / BN, MROWS / BM);              // 8 x 32
    gemm_bias_kernel<<<gE, 256>>>(query, q_w, q_b, pq, MROWS, EMB, EMB, scaling, 0);
    gemm_bias_kernel<<<gE, 256>>>(query, k_w, k_b, pk, MROWS, EMB, EMB, 1.f, 0);
    gemm_bias_kernel<<<gE, 256>>>(query, v_w, v_b, pv, MROWS, EMB, EMB, 1.f, 0);

    dim3 g1(MLP_H / BN, MROWS / BM);            // 4 x 32
    gemm_bias_kernel<<<g1, 256>>>(query, inf1_w, inf1_b, pt1, MROWS, MLP_H, EMB, 1.f, 1);

    mask_kernel<<<MROWS / 64, 256>>>(pt1, inf2_w, inf2_b, head_sig, pm);

    dim3 gf(S_LEN / 64, HEADS, BATCH);          // 32 x 16 x 2
    flash_kernel<<<gf, 256, FLASH_SMEM>>>(pq, pk, pv, pm, po);

    gemm_bias_kernel<<<gE, 256>>>(po, out_w, out_b, out, MROWS, EMB, EMB, 1.f, 0);
}

// round 3
// speedup vs baseline: 1.3715x; 1.3715x over previous
#include <cuda_runtime.h>
#include <cuda_bf16.h>
#include <cstdint>
#include <cstddef>

// Problem constants
#define S_LEN 2048
#define BATCH 2
#define EMB   1024
#define HEADS 16
#define HDIM  64
#define MROWS (S_LEN * BATCH)      // 4096
#define MLP_H 512
#define SIGD  64
#define KEEP  12                   // NUM_HEADS - INACTIVE

// ---------------- scratch (device globals; no allocation allowed) -------------
__device__ float g_q[MROWS * EMB];
__device__ float g_k[MROWS * EMB];
__device__ float g_v[MROWS * EMB];
__device__ float g_o[MROWS * EMB];
__device__ float g_t1[MROWS * MLP_H];
__device__ float g_mask[MROWS * HEADS];

// ======================= warp-level TF32 mma.sync helpers =====================
__device__ __forceinline__ void mma_tf32(float* c, const uint32_t* a,
                                         uint32_t b0, uint32_t b1)
{
    asm volatile(
        "mma.sync.aligned.m16n8k8.row.col.f32.tf32.tf32.f32 "
        "{%0,%1,%2,%3}, {%4,%5,%6,%7}, {%8,%9}, {%0,%1,%2,%3};"
        : "+f"(c[0]), "+f"(c[1]), "+f"(c[2]), "+f"(c[3])
        : "r"(a[0]), "r"(a[1]), "r"(a[2]), "r"(a[3]), "r"(b0), "r"(b1));
}

__device__ __forceinline__ uint32_t f2tf32(float f) {
    uint32_t u;
    asm("cvt.rna.tf32.f32 %0, %1;" : "=r"(u) : "f"(f));
    return u;
}
__device__ __forceinline__ uint4 cvt_tf32x4(float4 v) {
    uint4 u;
    u.x = f2tf32(v.x); u.y = f2tf32(v.y);
    u.z = f2tf32(v.z); u.w = f2tf32(v.w);
    return u;
}

// ==============================================================================
// TF32 mma.sync GEMM: C[M,N] = (A[M,K] @ W[N,K]^T + bias[N]) * scale
// 128x128x32 tile, 256 threads (8 warps, each 32m x 64n), double-buffered SMEM
// (padded stride 36 words -> conflict-free fragment reads).
// ==============================================================================
#define WBM 128
#define WBN 128
#define WBK 32
#define ASTR 36
#define TILE_WORDS (128 * ASTR)                 // 4608 words per tile
#define GEMM_MMA_SMEM (4 * TILE_WORDS * 4)      // A0,A1,B0,B1 = 73728 B

__global__ __launch_bounds__(256, 1) void gemm_tf32_mma_kernel(
    const float* __restrict__ A, const float* __restrict__ W,
    const float* __restrict__ bias, float* __restrict__ C,
    int M, int N, int K, float scale)
{
    extern __shared__ uint32_t smw[];
    uint32_t* Asm = smw;                       // [2][128][ASTR]
    uint32_t* Bsm = smw + 2 * TILE_WORDS;      // [2][128][ASTR]

    const int tid  = threadIdx.x;
    const int lane = tid & 31;
    const int wid  = tid >> 5;
    const int wm   = wid & 3;                  // m-offset wm*32
    const int wn   = wid >> 2;                 // n-offset wn*64
    const int g    = lane >> 2;
    const int t    = lane & 3;
    const int m0   = blockIdx.y * WBM;
    const int n0   = blockIdx.x * WBN;
    const int NB   = K / WBK;

    const int lrow = tid >> 3;                 // 0..31 per pass
    const int lc4  = (tid & 7) * 4;            // col within 32

    float c[2][8][4];
#pragma unroll
    for (int mf = 0; mf < 2; ++mf)
#pragma unroll
        for (int nf = 0; nf < 8; ++nf)
#pragma unroll
            for (int i = 0; i < 4; ++i) c[mf][nf][i] = 0.f;

    // prologue: stage K-block 0 into buffer 0
#pragma unroll
    for (int p = 0; p < 4; ++p) {
        int row = lrow + p * 32;
        float4 va = *(const float4*)&A[(size_t)(m0 + row) * K + lc4];
        float4 vb = *(const float4*)&W[(size_t)(n0 + row) * K + lc4];
        *(uint4*)&Asm[row * ASTR + lc4] = cvt_tf32x4(va);
        *(uint4*)&Bsm[row * ASTR + lc4] = cvt_tf32x4(vb);
    }
    __syncthreads();

    for (int kb = 0; kb < NB; ++kb) {
        const int b = kb & 1;
        const uint32_t* Ab = Asm + b * TILE_WORDS;
        const uint32_t* Bb = Bsm + b * TILE_WORDS;

        // issue global loads for next K-block (latency hidden behind the MMAs)
        float4 ra[4], rb[4];
        const bool pre = (kb + 1 < NB);
        if (pre) {
            const int kk = (kb + 1) * WBK;
#pragma unroll
            for (int p = 0; p < 4; ++p) {
                int row = lrow + p * 32;
                ra[p] = *(const float4*)&A[(size_t)(m0 + row) * K + kk + lc4];
                rb[p] = *(const float4*)&W[(size_t)(n0 + row) * K + kk + lc4];
            }
        }

        // MMAs on current buffer
#pragma unroll
        for (int ks = 0; ks < 4; ++ks) {
            uint32_t a[2][4];
#pragma unroll
            for (int mf = 0; mf < 2; ++mf) {
                int r  = wm * 32 + mf * 16 + g;
                int cc = ks * 8 + t;
                a[mf][0] = Ab[r * ASTR + cc];
                a[mf][1] = Ab[(r + 8) * ASTR + cc];
                a[mf][2] = Ab[r * ASTR + cc + 4];
                a[mf][3] = Ab[(r + 8) * ASTR + cc + 4];
            }
#pragma unroll
            for (int nf = 0; nf < 8; ++nf) {
                int r  = wn * 64 + nf * 8 + g;
                int cc = ks * 8 + t;
                uint32_t b0 = Bb[r * ASTR + cc];
                uint32_t b1 = Bb[r * ASTR + cc + 4];
                mma_tf32(c[0][nf], a[0], b0, b1);
                mma_tf32(c[1][nf], a[1], b0, b1);
            }
        }

        // store staged block into the other buffer
        if (pre) {
            uint32_t* An = Asm + (b ^ 1) * TILE_WORDS;
            uint32_t* Bn = Bsm + (b ^ 1) * TILE_WORDS;
#pragma unroll
            for (int p = 0; p < 4; ++p) {
                int row = lrow + p * 32;
                *(uint4*)&An[row * ASTR + lc4] = cvt_tf32x4(ra[p]);
                *(uint4*)&Bn[row * ASTR + lc4] = cvt_tf32x4(rb[p]);
            }
        }
        __syncthreads();
    }

    // epilogue: bias + scale, float2 stores (c0,c1 are adjacent columns)
#pragma unroll
    for (int mf = 0; mf < 2; ++mf) {
        int row0 = m0 + wm * 32 + mf * 16 + g;
#pragma unroll
        for (int nf = 0; nf < 8; ++nf) {
            int col = n0 + wn * 64 + nf * 8 + t * 2;
            float2 bv = *(const float2*)&bias[col];
            float2 r0, r1;
            r0.x = (c[mf][nf][0] + bv.x) * scale;
            r0.y = (c[mf][nf][1] + bv.y) * scale;
            r1.x = (c[mf][nf][2] + bv.x) * scale;
            r1.y = (c[mf][nf][3] + bv.y) * scale;
            *(float2*)&C[(size_t)row0 * N + col]       = r0;
            *(float2*)&C[(size_t)(row0 + 8) * N + col] = r1;
        }
    }
}

// ==============================================================================
// fp32 SIMT GEMM (mask path: top-k thresholding must stay exact)
// ==============================================================================
#define BM 128
#define BN 128
#define BK 16

__global__ __launch_bounds__(256) void gemm_bias_kernel(
    const float* __restrict__ A, const float* __restrict__ W,
    const float* __restrict__ bias, float* __restrict__ C,
    int M, int N, int K, float scale, int relu)
{
    __shared__ float As[BK][BM + 4];
    __shared__ float Bs[BK][BN + 4];

    const int tid = threadIdx.x;
    const int tx = tid & 15;
    const int ty = tid >> 4;
    const int m0 = blockIdx.y * BM;
    const int n0 = blockIdx.x * BN;

    float acc[8][8];
#pragma unroll
    for (int i = 0; i < 8; ++i)
#pragma unroll
        for (int j = 0; j < 8; ++j) acc[i][j] = 0.f;

    for (int kk = 0; kk < K; kk += BK) {
#pragma unroll
        for (int l = 0; l < 2; ++l) {
            int idx = tid + l * 256;
            int row = idx >> 2;
            int kc  = (idx & 3) * 4;
            float4 v = *(const float4*)&A[(size_t)(m0 + row) * K + kk + kc];
            As[kc + 0][row] = v.x; As[kc + 1][row] = v.y;
            As[kc + 2][row] = v.z; As[kc + 3][row] = v.w;
        }
#pragma unroll
        for (int l = 0; l < 2; ++l) {
            int idx = tid + l * 256;
            int row = idx >> 2;
            int kc  = (idx & 3) * 4;
            float4 v = *(const float4*)&W[(size_t)(n0 + row) * K + kk + kc];
            Bs[kc + 0][row] = v.x; Bs[kc + 1][row] = v.y;
            Bs[kc + 2][row] = v.z; Bs[kc + 3][row] = v.w;
        }
        __syncthreads();

#pragma unroll
        for (int k = 0; k < BK; ++k) {
            float a[8], b[8];
            *(float4*)&a[0] = *(const float4*)&As[k][ty * 8];
            *(float4*)&a[4] = *(const float4*)&As[k][ty * 8 + 4];
            *(float4*)&b[0] = *(const float4*)&Bs[k][tx * 8];
            *(float4*)&b[4] = *(const float4*)&Bs[k][tx * 8 + 4];
#pragma unroll
            for (int i = 0; i < 8; ++i)
#pragma unroll
                for (int j = 0; j < 8; ++j)
                    acc[i][j] = fmaf(a[i], b[j], acc[i][j]);
        }
        __syncthreads();
    }

#pragma unroll
    for (int i = 0; i < 8; ++i) {
        int m = m0 + ty * 8 + i;
#pragma unroll
        for (int j = 0; j < 8; j += 4) {
            int n = n0 + tx * 8 + j;
            float4 r;
            r.x = (acc[i][j + 0] + bias[n + 0]) * scale;
            r.y = (acc[i][j + 1] + bias[n + 1]) * scale;
            r.z = (acc[i][j + 2] + bias[n + 2]) * scale;
            r.w = (acc[i][j + 3] + bias[n + 3]) * scale;
            if (relu) {
                r.x = fmaxf(r.x, 0.f); r.y = fmaxf(r.y, 0.f);
                r.z = fmaxf(r.z, 0.f); r.w = fmaxf(r.w, 0.f);
            }
            *(float4*)&C[(size_t)m * N + n] = r;
        }
    }
}

// ==============================================================================
// Mask kernel (fp32 exact): t2 = t1 @ inf2_w^T + b2, scores, top-12 threshold.
// ==============================================================================
__global__ __launch_bounds__(256) void mask_kernel(
    const float* __restrict__ T1, const float* __restrict__ W2,
    const float* __restrict__ b2, const float* __restrict__ HS,
    float* __restrict__ maskOut)
{
    __shared__ float As[16][68];
    __shared__ float Ws[16][68];
    __shared__ float T2[64][68];
    __shared__ float HSs[16][68];
    __shared__ float Sc[64][16];

    const int tid = threadIdx.x;
    const int tx = tid & 15;
    const int ty = tid >> 4;
    const int m0 = blockIdx.x * 64;

    {
        int hrow = tid >> 4;
        int c4   = (tid & 15) * 4;
        float4 v = *(const float4*)&HS[(size_t)hrow * 64 + c4];
        *(float4*)&HSs[hrow][c4] = v;
    }

    float acc[4][4];
#pragma unroll
    for (int i = 0; i < 4; ++i)
#pragma unroll
        for (int j = 0; j < 4; ++j) acc[i][j] = 0.f;

    const int row = tid >> 2;
    const int kc  = (tid & 3) * 4;

    for (int kk = 0; kk < MLP_H; kk += 16) {
        float4 a = *(const float4*)&T1[(size_t)(m0 + row) * MLP_H + kk + kc];
        As[kc + 0][row] = a.x; As[kc + 1][row] = a.y;
        As[kc + 2][row] = a.z; As[kc + 3][row] = a.w;
        float4 w = *(const float4*)&W2[(size_t)row * MLP_H + kk + kc];
        Ws[kc + 0][row] = w.x; Ws[kc + 1][row] = w.y;
        Ws[kc + 2][row] = w.z; Ws[kc + 3][row] = w.w;
        __syncthreads();
#pragma unroll
        for (int k = 0; k < 16; ++k) {
            float a4[4], b4[4];
            *(float4*)&a4[0] = *(const float4*)&As[k][ty * 4];
            *(float4*)&b4[0] = *(const float4*)&Ws[k][tx * 4];
#pragma unroll
            for (int i = 0; i < 4; ++i)
#pragma unroll
                for (int j = 0; j < 4; ++j)
                    acc[i][j] = fmaf(a4[i], b4[j], acc[i][j]);
        }
        __syncthreads();
    }

#pragma unroll
    for (int i = 0; i < 4; ++i)
#pragma unroll
        for (int j = 0; j < 4; ++j)
            T2[ty * 4 + i][tx * 4 + j] = acc[i][j] + b2[tx * 4 + j];
    __syncthreads();

    {
        int r  = tid >> 2;
        int hg = (tid & 3) * 4;
        float sc[4] = {0.f, 0.f, 0.f, 0.f};
#pragma unroll 8
        for (int d = 0; d < 64; ++d) {
            float tv = T2[r][d];
            sc[0] = fmaf(tv, HSs[hg + 0][d], sc[0]);
            sc[1] = fmaf(tv, HSs[hg + 1][d], sc[1]);
            sc[2] = fmaf(tv, HSs[hg + 2][d], sc[2]);
            sc[3] = fmaf(tv, HSs[hg + 3][d], sc[3]);
        }
        *(float4*)&Sc[r][hg] = make_float4(sc[0], sc[1], sc[2], sc[3]);
    }
    __syncthreads();

    if (tid < 64) {
        float vals[16];
#pragma unroll
        for (int h = 0; h < 16; ++h) vals[h] = Sc[tid][h];
        bool used[16];
#pragma unroll
        for (int h = 0; h < 16; ++h) used[h] = false;
        float kth = -1e30f;
        for (int it = 0; it < KEEP; ++it) {
            float mx = -1e30f; int mi = 0;
            for (int h = 0; h < 16; ++h)
                if (!used[h] && vals[h] > mx) { mx = vals[h]; mi = h; }
            used[mi] = true;
            kth = mx;
        }
        for (int h = 0; h < 16; ++h)
            maskOut[(size_t)(m0 + tid) * HEADS + h] = (vals[h] >= kth) ? 1.f : 0.f;
    }
}

// ==============================================================================
// Flash attention (fp32, unchanged from R1 passing version)
// ==============================================================================
#define FPAD 68
#define FLASH_SMEM (4 * 64 * FPAD * 4)

__global__ __launch_bounds__(256) void flash_kernel(
    const float* __restrict__ Qg, const float* __restrict__ Kg,
    const float* __restrict__ Vg, const float* __restrict__ maskp,
    float* __restrict__ Og)
{
    extern __shared__ float sm[];
    float (*Qs)[FPAD] = (float(*)[FPAD])(sm);
    float (*Ks)[FPAD] = (float(*)[FPAD])(sm + 64 * FPAD);
    float (*Vs)[FPAD] = (float(*)[FPAD])(sm + 2 * 64 * FPAD);
    float (*Ps)[FPAD] = (float(*)[FPAD])(sm + 3 * 64 * FPAD);

    const int tid = threadIdx.x;
    const int tx = tid & 15;
    const int ty = tid >> 4;
    const int qt = blockIdx.x;
    const int h  = blockIdx.y;
    const int b  = blockIdx.z;
    const int s0 = qt * 64;
    const size_t rowstride = (size_t)BATCH * EMB;
    const size_t cbase = (size_t)b * EMB + (size_t)h * HDIM;

#pragma unroll
    for (int l = 0; l < 4; ++l) {
        int idx = tid + l * 256;
        int i   = idx >> 4;
        int c4  = (idx & 15) * 4;
        float4 v = *(const float4*)&Qg[(size_t)(s0 + i) * rowstride + cbase + c4];
        Qs[c4 + 0][i] = v.x; Qs[c4 + 1][i] = v.y;
        Qs[c4 + 2][i] = v.z; Qs[c4 + 3][i] = v.w;
    }

    float o[4][4];
    float mrow[4], lrow[4];
#pragma unroll
    for (int ii = 0; ii < 4; ++ii) {
        mrow[ii] = -1e30f; lrow[ii] = 0.f;
#pragma unroll
        for (int dd = 0; dd < 4; ++dd) o[ii][dd] = 0.f;
    }

    for (int kt = 0; kt < S_LEN / 64; ++kt) {
        __syncthreads();
#pragma unroll
        for (int l = 0; l < 4; ++l) {
            int idx = tid + l * 256;
            int j   = idx >> 4;
            int c4  = (idx & 15) * 4;
            size_t goff = (size_t)(kt * 64 + j) * rowstride + cbase + c4;
            float4 kv = *(const float4*)&Kg[goff];
            Ks[c4 + 0][j] = kv.x; Ks[c4 + 1][j] = kv.y;
            Ks[c4 + 2][j] = kv.z; Ks[c4 + 3][j] = kv.w;
            float4 vv = *(const float4*)&Vg[goff];
            *(float4*)&Vs[j][c4] = vv;
        }
        __syncthreads();

        float sv[4][4];
#pragma unroll
        for (int ii = 0; ii < 4; ++ii)
#pragma unroll
            for (int jj = 0; jj < 4; ++jj) sv[ii][jj] = 0.f;

#pragma unroll 8
        for (int d = 0; d < 64; ++d) {
            float qa[4], ka[4];
            *(float4*)&qa[0] = *(const float4*)&Qs[d][ty * 4];
            *(float4*)&ka[0] = *(const float4*)&Ks[d][tx * 4];
#pragma unroll
            for (int ii = 0; ii < 4; ++ii)
#pragma unroll
                for (int jj = 0; jj < 4; ++jj)
                    sv[ii][jj] = fmaf(qa[ii], ka[jj], sv[ii][jj]);
        }

#pragma unroll
        for (int ii = 0; ii < 4; ++ii) {
            float tm = fmaxf(fmaxf(sv[ii][0], sv[ii][1]), fmaxf(sv[ii][2], sv[ii][3]));
#pragma unroll
            for (int off = 1; off < 16; off <<= 1)
                tm = fmaxf(tm, __shfl_xor_sync(0xffffffffu, tm, off));
            float mnew  = fmaxf(mrow[ii], tm);
            float alpha = __expf(mrow[ii] - mnew);
            float ls = 0.f;
#pragma unroll
            for (int jj = 0; jj < 4; ++jj) {
                sv[ii][jj] = __expf(sv[ii][jj] - mnew);
                ls += sv[ii][jj];
            }
#pragma unroll
            for (int off = 1; off < 16; off <<= 1)
                ls += __shfl_xor_sync(0xffffffffu, ls, off);
            lrow[ii] = lrow[ii] * alpha + ls;
            mrow[ii] = mnew;
#pragma unroll
            for (int dd = 0; dd < 4; ++dd) o[ii][dd] *= alpha;
            *(float4*)&Ps[ty * 4 + ii][tx * 4] =
                make_float4(sv[ii][0], sv[ii][1], sv[ii][2], sv[ii][3]);
        }
        __syncthreads();

#pragma unroll 4
        for (int j4 = 0; j4 < 16; ++j4) {
            float vv[4][4];
#pragma unroll
            for (int jj = 0; jj < 4; ++jj)
                *(float4*)&vv[jj][0] = *(const float4*)&Vs[j4 * 4 + jj][tx * 4];
#pragma unroll
            for (int ii = 0; ii < 4; ++ii) {
                float p[4];
                *(float4*)&p[0] = *(const float4*)&Ps[ty * 4 + ii][j4 * 4];
#pragma unroll
                for (int jj = 0; jj < 4; ++jj)
#pragma unroll
                    for (int dd = 0; dd < 4; ++dd)
                        o[ii][dd] = fmaf(p[jj], vv[jj][dd], o[ii][dd]);
            }
        }
    }

#pragma unroll
    for (int ii = 0; ii < 4; ++ii) {
        int i = ty * 4 + ii;
        int srow = s0 + i;
        float mval = maskp[((size_t)srow * BATCH + b) * HEADS + h];
        float inv  = mval / lrow[ii];
        float4 r;
        r.x = o[ii][0] * inv; r.y = o[ii][1] * inv;
        r.z = o[ii][2] * inv; r.w = o[ii][3] * inv;
        *(float4*)&Og[(size_t)srow * rowstride + cbase + tx * 4] = r;
    }
}

// ==============================================================================
// launch
// ==============================================================================
extern "C" void kernel_launch(void* const* d_in, const int* in_sizes, int n_in,
                              void* d_out, int out_size)
{
    (void)in_sizes; (void)n_in; (void)out_size;
    const float* query   = (const float*)d_in[0];
    const float* q_w     = (const float*)d_in[1];
    const float* q_b     = (const float*)d_in[2];
    const float* k_w     = (const float*)d_in[3];
    const float* k_b     = (const float*)d_in[4];
    const float* v_w     = (const float*)d_in[5];
    const float* v_b     = (const float*)d_in[6];
    const float* out_w   = (const float*)d_in[7];
    const float* out_b   = (const float*)d_in[8];
    const float* inf1_w  = (const float*)d_in[9];
    const float* inf1_b  = (const float*)d_in[10];
    const float* inf2_w  = (const float*)d_in[11];
    const float* inf2_b  = (const float*)d_in[12];
    const float* head_sig= (const float*)d_in[13];
    float* out = (float*)d_out;

    float* pq;  cudaGetSymbolAddress((void**)&pq,  g_q);
    float* pk;  cudaGetSymbolAddress((void**)&pk,  g_k);
    float* pv;  cudaGetSymbolAddress((void**)&pv,  g_v);
    float* po;  cudaGetSymbolAddress((void**)&po,  g_o);
    float* pt1; cudaGetSymbolAddress((void**)&pt1, g_t1);
    float* pm;  cudaGetSymbolAddress((void**)&pm,  g_mask);

    cudaFuncSetAttribute(flash_kernel,
                         cudaFuncAttributeMaxDynamicSharedMemorySize, FLASH_SMEM);
    cudaFuncSetAttribute(gemm_tf32_mma_kernel,
                         cudaFuncAttributeMaxDynamicSharedMemorySize, GEMM_MMA_SMEM);

    const float scaling = 0.125f;   // 64^-0.5

    // q/k/v projections on TF32 mma.sync tensor cores
    dim3 gT(EMB / WBN, MROWS / WBM);            // 8 x 32
    gemm_tf32_mma_kernel<<<gT, 256, GEMM_MMA_SMEM>>>(query, q_w, q_b, pq, MROWS, EMB, EMB, scaling);
    gemm_tf32_mma_kernel<<<gT, 256, GEMM_MMA_SMEM>>>(query, k_w, k_b, pk, MROWS, EMB, EMB, 1.f);
    gemm_tf32_mma_kernel<<<gT, 256, GEMM_MMA_SMEM>>>(query, v_w, v_b, pv, MROWS, EMB, EMB, 1.f);

    // mask path stays exact fp32 (top-k threshold sensitivity)
    dim3 g1(MLP_H / BN, MROWS / BM);            // 4 x 32
    gemm_bias_kernel<<<g1, 256>>>(query, inf1_w, inf1_b, pt1, MROWS, MLP_H, EMB, 1.f, 1);
    mask_kernel<<<MROWS / 64, 256>>>(pt1, inf2_w, inf2_b, head_sig, pm);

    dim3 gf(S_LEN / 64, HEADS, BATCH);          // 32 x 16 x 2
    flash_kernel<<<gf, 256, FLASH_SMEM>>>(pq, pk, pv, pm, po);

    // out projection on TF32 mma.sync
    gemm_tf32_mma_kernel<<<gT, 256, GEMM_MMA_SMEM>>>(po, out_w, out_b, out, MROWS, EMB, EMB, 1.f);
}

// round 4
// speedup vs baseline: 2.4131x; 1.7594x over previous
#include <cuda_runtime.h>
#include <cuda_bf16.h>
#include <cuda_fp16.h>
#include <cstdint>
#include <cstddef>

// Problem constants
#define S_LEN 2048
#define BATCH 2
#define EMB   1024
#define HEADS 16
#define HDIM  64
#define MROWS (S_LEN * BATCH)      // 4096
#define MLP_H 512
#define SIGD  64
#define KEEP  12                   // NUM_HEADS - INACTIVE

// ---------------- scratch (device globals; no allocation allowed) -------------
__device__ float g_q[MROWS * EMB];
__device__ float g_k[MROWS * EMB];
__device__ float g_v[MROWS * EMB];
__device__ float g_o[MROWS * EMB];
__device__ float g_t1[MROWS * MLP_H];
__device__ float g_mask[MROWS * HEADS];

// ======================= warp-level mma.sync helpers ==========================
__device__ __forceinline__ void mma_tf32(float* c, const uint32_t* a,
                                         uint32_t b0, uint32_t b1)
{
    asm volatile(
        "mma.sync.aligned.m16n8k8.row.col.f32.tf32.tf32.f32 "
        "{%0,%1,%2,%3}, {%4,%5,%6,%7}, {%8,%9}, {%0,%1,%2,%3};"
        : "+f"(c[0]), "+f"(c[1]), "+f"(c[2]), "+f"(c[3])
        : "r"(a[0]), "r"(a[1]), "r"(a[2]), "r"(a[3]), "r"(b0), "r"(b1));
}

__device__ __forceinline__ void mma_f16(float* c, const uint32_t* a,
                                        uint32_t b0, uint32_t b1)
{
    asm volatile(
        "mma.sync.aligned.m16n8k16.row.col.f32.f16.f16.f32 "
        "{%0,%1,%2,%3}, {%4,%5,%6,%7}, {%8,%9}, {%0,%1,%2,%3};"
        : "+f"(c[0]), "+f"(c[1]), "+f"(c[2]), "+f"(c[3])
        : "r"(a[0]), "r"(a[1]), "r"(a[2]), "r"(a[3]), "r"(b0), "r"(b1));
}

__device__ __forceinline__ uint32_t f2tf32(float f) {
    uint32_t u;
    asm("cvt.rna.tf32.f32 %0, %1;" : "=r"(u) : "f"(f));
    return u;
}
__device__ __forceinline__ uint4 cvt_tf32x4(float4 v) {
    uint4 u;
    u.x = f2tf32(v.x); u.y = f2tf32(v.y);
    u.z = f2tf32(v.z); u.w = f2tf32(v.w);
    return u;
}
__device__ __forceinline__ uint32_t pack_h2(__half a, __half b) {
    __half2 h = __halves2half2(a, b);
    return *(uint32_t*)&h;
}

// ==============================================================================
// TF32 mma.sync GEMM: C[M,N] = (A[M,K] @ W[N,K]^T + bias[N]) * scale
// ==============================================================================
#define WBM 128
#define WBN 128
#define WBK 32
#define ASTR 36
#define TILE_WORDS (128 * ASTR)
#define GEMM_MMA_SMEM (4 * TILE_WORDS * 4)      // 73728 B

__global__ __launch_bounds__(256, 1) void gemm_tf32_mma_kernel(
    const float* __restrict__ A, const float* __restrict__ W,
    const float* __restrict__ bias, float* __restrict__ C,
    int M, int N, int K, float scale)
{
    extern __shared__ uint32_t smw[];
    uint32_t* Asm = smw;
    uint32_t* Bsm = smw + 2 * TILE_WORDS;

    const int tid  = threadIdx.x;
    const int lane = tid & 31;
    const int wid  = tid >> 5;
    const int wm   = wid & 3;
    const int wn   = wid >> 2;
    const int g    = lane >> 2;
    const int t    = lane & 3;
    const int m0   = blockIdx.y * WBM;
    const int n0   = blockIdx.x * WBN;
    const int NB   = K / WBK;

    const int lrow = tid >> 3;
    const int lc4  = (tid & 7) * 4;

    float c[2][8][4];
#pragma unroll
    for (int mf = 0; mf < 2; ++mf)
#pragma unroll
        for (int nf = 0; nf < 8; ++nf)
#pragma unroll
            for (int i = 0; i < 4; ++i) c[mf][nf][i] = 0.f;

#pragma unroll
    for (int p = 0; p < 4; ++p) {
        int row = lrow + p * 32;
        float4 va = *(const float4*)&A[(size_t)(m0 + row) * K + lc4];
        float4 vb = *(const float4*)&W[(size_t)(n0 + row) * K + lc4];
        *(uint4*)&Asm[row * ASTR + lc4] = cvt_tf32x4(va);
        *(uint4*)&Bsm[row * ASTR + lc4] = cvt_tf32x4(vb);
    }
    __syncthreads();

    for (int kb = 0; kb < NB; ++kb) {
        const int b = kb & 1;
        const uint32_t* Ab = Asm + b * TILE_WORDS;
        const uint32_t* Bb = Bsm + b * TILE_WORDS;

        float4 ra[4], rb[4];
        const bool pre = (kb + 1 < NB);
        if (pre) {
            const int kk = (kb + 1) * WBK;
#pragma unroll
            for (int p = 0; p < 4; ++p) {
                int row = lrow + p * 32;
                ra[p] = *(const float4*)&A[(size_t)(m0 + row) * K + kk + lc4];
                rb[p] = *(const float4*)&W[(size_t)(n0 + row) * K + kk + lc4];
            }
        }

#pragma unroll
        for (int ks = 0; ks < 4; ++ks) {
            uint32_t a[2][4];
#pragma unroll
            for (int mf = 0; mf < 2; ++mf) {
                int r  = wm * 32 + mf * 16 + g;
                int cc = ks * 8 + t;
                a[mf][0] = Ab[r * ASTR + cc];
                a[mf][1] = Ab[(r + 8) * ASTR + cc];
                a[mf][2] = Ab[r * ASTR + cc + 4];
                a[mf][3] = Ab[(r + 8) * ASTR + cc + 4];
            }
#pragma unroll
            for (int nf = 0; nf < 8; ++nf) {
                int r  = wn * 64 + nf * 8 + g;
                int cc = ks * 8 + t;
                uint32_t b0 = Bb[r * ASTR + cc];
                uint32_t b1 = Bb[r * ASTR + cc + 4];
                mma_tf32(c[0][nf], a[0], b0, b1);
                mma_tf32(c[1][nf], a[1], b0, b1);
            }
        }

        if (pre) {
            uint32_t* An = Asm + (b ^ 1) * TILE_WORDS;
            uint32_t* Bn = Bsm + (b ^ 1) * TILE_WORDS;
#pragma unroll
            for (int p = 0; p < 4; ++p) {
                int row = lrow + p * 32;
                *(uint4*)&An[row * ASTR + lc4] = cvt_tf32x4(ra[p]);
                *(uint4*)&Bn[row * ASTR + lc4] = cvt_tf32x4(rb[p]);
            }
        }
        __syncthreads();
    }

#pragma unroll
    for (int mf = 0; mf < 2; ++mf) {
        int row0 = m0 + wm * 32 + mf * 16 + g;
#pragma unroll
        for (int nf = 0; nf < 8; ++nf) {
            int col = n0 + wn * 64 + nf * 8 + t * 2;
            float2 bv = *(const float2*)&bias[col];
            float2 r0, r1;
            r0.x = (c[mf][nf][0] + bv.x) * scale;
            r0.y = (c[mf][nf][1] + bv.y) * scale;
            r1.x = (c[mf][nf][2] + bv.x) * scale;
            r1.y = (c[mf][nf][3] + bv.y) * scale;
            *(float2*)&C[(size_t)row0 * N + col]       = r0;
            *(float2*)&C[(size_t)(row0 + 8) * N + col] = r1;
        }
    }
}

// ==============================================================================
// fp32 SIMT GEMM (mask path: top-k thresholding must stay exact)
// ==============================================================================
#define BM 128
#define BN 128
#define BK 16

__global__ __launch_bounds__(256) void gemm_bias_kernel(
    const float* __restrict__ A, const float* __restrict__ W,
    const float* __restrict__ bias, float* __restrict__ C,
    int M, int N, int K, float scale, int relu)
{
    __shared__ float As[BK][BM + 4];
    __shared__ float Bs[BK][BN + 4];

    const int tid = threadIdx.x;
    const int tx = tid & 15;
    const int ty = tid >> 4;
    const int m0 = blockIdx.y * BM;
    const int n0 = blockIdx.x * BN;

    float acc[8][8];
#pragma unroll
    for (int i = 0; i < 8; ++i)
#pragma unroll
        for (int j = 0; j < 8; ++j) acc[i][j] = 0.f;

    for (int kk = 0; kk < K; kk += BK) {
#pragma unroll
        for (int l = 0; l < 2; ++l) {
            int idx = tid + l * 256;
            int row = idx >> 2;
            int kc  = (idx & 3) * 4;
            float4 v = *(const float4*)&A[(size_t)(m0 + row) * K + kk + kc];
            As[kc + 0][row] = v.x; As[kc + 1][row] = v.y;
            As[kc + 2][row] = v.z; As[kc + 3][row] = v.w;
        }
#pragma unroll
        for (int l = 0; l < 2; ++l) {
            int idx = tid + l * 256;
            int row = idx >> 2;
            int kc  = (idx & 3) * 4;
            float4 v = *(const float4*)&W[(size_t)(n0 + row) * K + kk + kc];
            Bs[kc + 0][row] = v.x; Bs[kc + 1][row] = v.y;
            Bs[kc + 2][row] = v.z; Bs[kc + 3][row] = v.w;
        }
        __syncthreads();

#pragma unroll
        for (int k = 0; k < BK; ++k) {
            float a[8], b[8];
            *(float4*)&a[0] = *(const float4*)&As[k][ty * 8];
            *(float4*)&a[4] = *(const float4*)&As[k][ty * 8 + 4];
            *(float4*)&b[0] = *(const float4*)&Bs[k][tx * 8];
            *(float4*)&b[4] = *(const float4*)&Bs[k][tx * 8 + 4];
#pragma unroll
            for (int i = 0; i < 8; ++i)
#pragma unroll
                for (int j = 0; j < 8; ++j)
                    acc[i][j] = fmaf(a[i], b[j], acc[i][j]);
        }
        __syncthreads();
    }

#pragma unroll
    for (int i = 0; i < 8; ++i) {
        int m = m0 + ty * 8 + i;
#pragma unroll
        for (int j = 0; j < 8; j += 4) {
            int n = n0 + tx * 8 + j;
            float4 r;
            r.x = (acc[i][j + 0] + bias[n + 0]) * scale;
            r.y = (acc[i][j + 1] + bias[n + 1]) * scale;
            r.z = (acc[i][j + 2] + bias[n + 2]) * scale;
            r.w = (acc[i][j + 3] + bias[n + 3]) * scale;
            if (relu) {
                r.x = fmaxf(r.x, 0.f); r.y = fmaxf(r.y, 0.f);
                r.z = fmaxf(r.z, 0.f); r.w = fmaxf(r.w, 0.f);
            }
            *(float4*)&C[(size_t)m * N + n] = r;
        }
    }
}

// ==============================================================================
// Mask kernel (fp32 exact)
// ==============================================================================
__global__ __launch_bounds__(256) void mask_kernel(
    const float* __restrict__ T1, const float* __restrict__ W2,
    const float* __restrict__ b2, const float* __restrict__ HS,
    float* __restrict__ maskOut)
{
    __shared__ float As[16][68];
    __shared__ float Ws[16][68];
    __shared__ float T2[64][68];
    __shared__ float HSs[16][68];
    __shared__ float Sc[64][16];

    const int tid = threadIdx.x;
    const int tx = tid & 15;
    const int ty = tid >> 4;
    const int m0 = blockIdx.x * 64;

    {
        int hrow = tid >> 4;
        int c4   = (tid & 15) * 4;
        float4 v = *(const float4*)&HS[(size_t)hrow * 64 + c4];
        *(float4*)&HSs[hrow][c4] = v;
    }

    float acc[4][4];
#pragma unroll
    for (int i = 0; i < 4; ++i)
#pragma unroll
        for (int j = 0; j < 4; ++j) acc[i][j] = 0.f;

    const int row = tid >> 2;
    const int kc  = (tid & 3) * 4;

    for (int kk = 0; kk < MLP_H; kk += 16) {
        float4 a = *(const float4*)&T1[(size_t)(m0 + row) * MLP_H + kk + kc];
        As[kc + 0][row] = a.x; As[kc + 1][row] = a.y;
        As[kc + 2][row] = a.z; As[kc + 3][row] = a.w;
        float4 w = *(const float4*)&W2[(size_t)row * MLP_H + kk + kc];
        Ws[kc + 0][row] = w.x; Ws[kc + 1][row] = w.y;
        Ws[kc + 2][row] = w.z; Ws[kc + 3][row] = w.w;
        __syncthreads();
#pragma unroll
        for (int k = 0; k < 16; ++k) {
            float a4[4], b4[4];
            *(float4*)&a4[0] = *(const float4*)&As[k][ty * 4];
            *(float4*)&b4[0] = *(const float4*)&Ws[k][tx * 4];
#pragma unroll
            for (int i = 0; i < 4; ++i)
#pragma unroll
                for (int j = 0; j < 4; ++j)
                    acc[i][j] = fmaf(a4[i], b4[j], acc[i][j]);
        }
        __syncthreads();
    }

#pragma unroll
    for (int i = 0; i < 4; ++i)
#pragma unroll
        for (int j = 0; j < 4; ++j)
            T2[ty * 4 + i][tx * 4 + j] = acc[i][j] + b2[tx * 4 + j];
    __syncthreads();

    {
        int r  = tid >> 2;
        int hg = (tid & 3) * 4;
        float sc[4] = {0.f, 0.f, 0.f, 0.f};
#pragma unroll 8
        for (int d = 0; d < 64; ++d) {
            float tv = T2[r][d];
            sc[0] = fmaf(tv, HSs[hg + 0][d], sc[0]);
            sc[1] = fmaf(tv, HSs[hg + 1][d], sc[1]);
            sc[2] = fmaf(tv, HSs[hg + 2][d], sc[2]);
            sc[3] = fmaf(tv, HSs[hg + 3][d], sc[3]);
        }
        *(float4*)&Sc[r][hg] = make_float4(sc[0], sc[1], sc[2], sc[3]);
    }
    __syncthreads();

    if (tid < 64) {
        float vals[16];
#pragma unroll
        for (int h = 0; h < 16; ++h) vals[h] = Sc[tid][h];
        bool used[16];
#pragma unroll
        for (int h = 0; h < 16; ++h) used[h] = false;
        float kth = -1e30f;
        for (int it = 0; it < KEEP; ++it) {
            float mx = -1e30f; int mi = 0;
            for (int h = 0; h < 16; ++h)
                if (!used[h] && vals[h] > mx) { mx = vals[h]; mi = h; }
            used[mi] = true;
            kth = mx;
        }
        for (int h = 0; h < 16; ++h)
            maskOut[(size_t)(m0 + tid) * HEADS + h] = (vals[h] >= kth) ? 1.f : 0.f;
    }
}

// ==============================================================================
// Flash attention on tensor cores.
// QK^T: split fp16 (3-term, near-fp32 accuracy).  P*V: single TF32.
// CTA: 128 q-rows x one (b,h). 8 warps, each 16 q-rows x full 64-col kv tile.
// K(hi/lo) and V double-buffered in SMEM with register prefetch.
// ==============================================================================
#define KST2 36     // K half2-pair stride (32 pairs + pad)
#define VST  72     // V tf32 stride
#define PST  68     // P tf32 stride

#define OFF_KSH 0
#define OFF_KSL (2 * 64 * KST2)
#define OFF_VS  (OFF_KSL + 2 * 64 * KST2)
#define OFF_PS  (OFF_VS + 2 * 64 * VST)
#define FLASH2_WORDS (OFF_PS + 128 * PST)
#define FLASH2_SMEM (FLASH2_WORDS * 4)   // (4608+4608+9216+8704)*4 = 108544 B

__global__ __launch_bounds__(256, 1) void flash_mma_kernel(
    const float* __restrict__ Qg, const float* __restrict__ Kg,
    const float* __restrict__ Vg, const float* __restrict__ maskp,
    float* __restrict__ Og)
{
    extern __shared__ uint32_t smf[];
    uint32_t* Ksh = smf + OFF_KSH;
    uint32_t* Ksl = smf + OFF_KSL;
    uint32_t* Vss = smf + OFF_VS;
    uint32_t* Pss = smf + OFF_PS;

    const int tid  = threadIdx.x;
    const int lane = tid & 31;
    const int wid  = tid >> 5;
    const int g    = lane >> 2;
    const int t    = lane & 3;
    const int mbase = wid * 16;

    const int qt = blockIdx.x;
    const int h  = blockIdx.y;
    const int b  = blockIdx.z;
    const int s0 = qt * 128;
    const size_t rowstride = (size_t)BATCH * EMB;   // 2048
    const size_t cbase = (size_t)b * EMB + (size_t)h * HDIM;

    // ---- stage Q tile (128x64 fp32) into Ps region, coalesced ----
    float* Qst = (float*)Pss;
#pragma unroll
    for (int p = 0; p < 8; ++p) {
        int idx = tid + p * 256;
        int row = idx >> 4;
        int c4  = (idx & 15) * 4;
        float4 v = *(const float4*)&Qg[(size_t)(s0 + row) * rowstride + cbase + c4];
        *(float4*)&Qst[row * PST + c4] = v;
    }
    __syncthreads();

    // ---- build Q fragments (split fp16 hi/lo), register resident ----
    uint32_t qh[4][4], ql[4][4];
#pragma unroll
    for (int ks = 0; ks < 4; ++ks) {
        int r0 = mbase + g, r1 = mbase + g + 8;
        int c0 = ks * 16 + 2 * t;
#pragma unroll
        for (int fi = 0; fi < 4; ++fi) {
            int rr = (fi & 1) ? r1 : r0;
            int cc = c0 + ((fi >> 1) ? 8 : 0);
            float f0 = Qst[rr * PST + cc];
            float f1 = Qst[rr * PST + cc + 1];
            __half h0 = __float2half_rn(f0);
            __half h1 = __float2half_rn(f1);
            __half l0 = __float2half_rn(f0 - __half2float(h0));
            __half l1 = __float2half_rn(f1 - __half2float(h1));
            qh[ks][fi] = pack_h2(h0, h1);
            ql[ks][fi] = pack_h2(l0, l1);
        }
    }

    // ---- K/V tile loader helpers ----
    const int lrow = tid >> 4;          // 0..15 (+16p)
    const int lc4  = (tid & 15) * 4;    // d-col base
    float4 kr[4], vr[4];

    auto load_kv = [&](int kt) {
#pragma unroll
        for (int p = 0; p < 4; ++p) {
            int row = lrow + p * 16;
            size_t goff = (size_t)(kt * 64 + row) * rowstride + cbase + lc4;
            kr[p] = *(const float4*)&Kg[goff];
            vr[p] = *(const float4*)&Vg[goff];
        }
    };
    auto store_kv = [&](int bb) {
        uint32_t* Kh = Ksh + bb * 64 * KST2;
        uint32_t* Kl = Ksl + bb * 64 * KST2;
        uint32_t* Vb = Vss + bb * 64 * VST;
#pragma unroll
        for (int p = 0; p < 4; ++p) {
            int row = lrow + p * 16;
            float f[4] = {kr[p].x, kr[p].y, kr[p].z, kr[p].w};
            __half hh[4], hl[4];
#pragma unroll
            for (int e = 0; e < 4; ++e) {
                hh[e] = __float2half_rn(f[e]);
                hl[e] = __float2half_rn(f[e] - __half2float(hh[e]));
            }
            int pr = (tid & 15) * 2;
            Kh[row * KST2 + pr]     = pack_h2(hh[0], hh[1]);
            Kh[row * KST2 + pr + 1] = pack_h2(hh[2], hh[3]);
            Kl[row * KST2 + pr]     = pack_h2(hl[0], hl[1]);
            Kl[row * KST2 + pr + 1] = pack_h2(hl[2], hl[3]);
            *(uint4*)&Vb[row * VST + lc4] = cvt_tf32x4(vr[p]);
        }
    };

    load_kv(0);
    store_kv(0);
    __syncthreads();   // KV tile 0 visible; all Q-frag reads of Ps done

    float o[8][4];
    float m0r = -1e30f, m1r = -1e30f, l0r = 0.f, l1r = 0.f;
#pragma unroll
    for (int nf = 0; nf < 8; ++nf)
#pragma unroll
        for (int i = 0; i < 4; ++i) o[nf][i] = 0.f;

    const int NKT = S_LEN / 64;   // 32
    for (int kt = 0; kt < NKT; ++kt) {
        const int bb = kt & 1;
        const uint32_t* Kh = Ksh + bb * 64 * KST2;
        const uint32_t* Kl = Ksl + bb * 64 * KST2;
        const uint32_t* Vb = Vss + bb * 64 * VST;

        // ---- S = Q K^T  (split fp16: hh + lh + hl) ----
        float sc[8][4];
#pragma unroll
        for (int nf = 0; nf < 8; ++nf)
#pragma unroll
            for (int i = 0; i < 4; ++i) sc[nf][i] = 0.f;

#pragma unroll
        for (int ks = 0; ks < 4; ++ks) {
#pragma unroll
            for (int nf = 0; nf < 8; ++nf) {
                int krow = nf * 8 + g;
                uint32_t b0h = Kh[krow * KST2 + ks * 8 + t];
                uint32_t b1h = Kh[krow * KST2 + ks * 8 + t + 4];
                uint32_t b0l = Kl[krow * KST2 + ks * 8 + t];
                uint32_t b1l = Kl[krow * KST2 + ks * 8 + t + 4];
                mma_f16(sc[nf], qh[ks], b0h, b1h);
                mma_f16(sc[nf], ql[ks], b0h, b1h);
                mma_f16(sc[nf], qh[ks], b0l, b1l);
            }
        }

        // prefetch next K/V tile (global loads overlap softmax + PV)
        if (kt + 1 < NKT) load_kv(kt + 1);

        // ---- online softmax (rows g and g+8; stats shared across quad) ----
        float tm0 = -1e30f, tm1 = -1e30f;
#pragma unroll
        for (int nf = 0; nf < 8; ++nf) {
            tm0 = fmaxf(tm0, fmaxf(sc[nf][0], sc[nf][1]));
            tm1 = fmaxf(tm1, fmaxf(sc[nf][2], sc[nf][3]));
        }
        tm0 = fmaxf(tm0, __shfl_xor_sync(0xffffffffu, tm0, 1));
        tm0 = fmaxf(tm0, __shfl_xor_sync(0xffffffffu, tm0, 2));
        tm1 = fmaxf(tm1, __shfl_xor_sync(0xffffffffu, tm1, 1));
        tm1 = fmaxf(tm1, __shfl_xor_sync(0xffffffffu, tm1, 2));

        float mn0 = fmaxf(m0r, tm0);
        float mn1 = fmaxf(m1r, tm1);
        float al0 = __expf(m0r - mn0);
        float al1 = __expf(m1r - mn1);

        float ls0 = 0.f, ls1 = 0.f;
#pragma unroll
        for (int nf = 0; nf < 8; ++nf) {
            sc[nf][0] = __expf(sc[nf][0] - mn0);
            sc[nf][1] = __expf(sc[nf][1] - mn0);
            sc[nf][2] = __expf(sc[nf][2] - mn1);
            sc[nf][3] = __expf(sc[nf][3] - mn1);
            ls0 += sc[nf][0] + sc[nf][1];
            ls1 += sc[nf][2] + sc[nf][3];
        }
        ls0 += __shfl_xor_sync(0xffffffffu, ls0, 1);
        ls0 += __shfl_xor_sync(0xffffffffu, ls0, 2);
        ls1 += __shfl_xor_sync(0xffffffffu, ls1, 1);
        ls1 += __shfl_xor_sync(0xffffffffu, ls1, 2);

        l0r = l0r * al0 + ls0;  m0r = mn0;
        l1r = l1r * al1 + ls1;  m1r = mn1;

#pragma unroll
        for (int nf = 0; nf < 8; ++nf) {
            o[nf][0] *= al0; o[nf][1] *= al0;
            o[nf][2] *= al1; o[nf][3] *= al1;
        }

        // ---- store P to smem (tf32) ----
#pragma unroll
        for (int nf = 0; nf < 8; ++nf) {
            int col = nf * 8 + 2 * t;
            uint2 p0 = make_uint2(f2tf32(sc[nf][0]), f2tf32(sc[nf][1]));
            uint2 p1 = make_uint2(f2tf32(sc[nf][2]), f2tf32(sc[nf][3]));
            *(uint2*)&Pss[(mbase + g) * PST + col]     = p0;
            *(uint2*)&Pss[(mbase + g + 8) * PST + col] = p1;
        }

        // store prefetched K/V into the other buffer
        if (kt + 1 < NKT) store_kv(bb ^ 1);

        __syncthreads();   // Ps visible; next buffer ready

        // ---- O += P V  (tf32) ----
#pragma unroll
        for (int ks = 0; ks < 8; ++ks) {
            uint32_t a[4];
            a[0] = Pss[(mbase + g) * PST + ks * 8 + t];
            a[1] = Pss[(mbase + g + 8) * PST + ks * 8 + t];
            a[2] = Pss[(mbase + g) * PST + ks * 8 + t + 4];
            a[3] = Pss[(mbase + g + 8) * PST + ks * 8 + t + 4];
#pragma unroll
            for (int nf = 0; nf < 8; ++nf) {
                uint32_t b0 = Vb[(ks * 8 + t) * VST + nf * 8 + g];
                uint32_t b1 = Vb[(ks * 8 + t + 4) * VST + nf * 8 + g];
                mma_tf32(o[nf], a, b0, b1);
            }
        }
        __syncthreads();   // all reads of Ps / Vs[bb] done
    }

    // ---- epilogue: normalize, head-gate, write (S,B,E) ----
    int srow0 = s0 + mbase + g;
    int srow1 = srow0 + 8;
    float mv0 = maskp[((size_t)srow0 * BATCH + b) * HEADS + h];
    float mv1 = maskp[((size_t)srow1 * BATCH + b) * HEADS + h];
    float inv0 = mv0 / l0r;
    float inv1 = mv1 / l1r;
#pragma unroll
    for (int nf = 0; nf < 8; ++nf) {
        int col = nf * 8 + 2 * t;
        float2 r0 = make_float2(o[nf][0] * inv0, o[nf][1] * inv0);
        float2 r1 = make_float2(o[nf][2] * inv1, o[nf][3] * inv1);
        *(float2*)&Og[(size_t)srow0 * rowstride + cbase + col] = r0;
        *(float2*)&Og[(size_t)srow1 * rowstride + cbase + col] = r1;
    }
}

// ==============================================================================
// launch
// ==============================================================================
extern "C" void kernel_launch(void* const* d_in, const int* in_sizes, int n_in,
                              void* d_out, int out_size)
{
    (void)in_sizes; (void)n_in; (void)out_size;
    const float* query   = (const float*)d_in[0];
    const float* q_w     = (const float*)d_in[1];
    const float* q_b     = (const float*)d_in[2];
    const float* k_w     = (const float*)d_in[3];
    const float* k_b     = (const float*)d_in[4];
    const float* v_w     = (const float*)d_in[5];
    const float* v_b     = (const float*)d_in[6];
    const float* out_w   = (const float*)d_in[7];
    const float* out_b   = (const float*)d_in[8];
    const float* inf1_w  = (const float*)d_in[9];
    const float* inf1_b  = (const float*)d_in[10];
    const float* inf2_w  = (const float*)d_in[11];
    const float* inf2_b  = (const float*)d_in[12];
    const float* head_sig= (const float*)d_in[13];
    float* out = (float*)d_out;

    float* pq;  cudaGetSymbolAddress((void**)&pq,  g_q);
    float* pk;  cudaGetSymbolAddress((void**)&pk,  g_k);
    float* pv;  cudaGetSymbolAddress((void**)&pv,  g_v);
    float* po;  cudaGetSymbolAddress((void**)&po,  g_o);
    float* pt1; cudaGetSymbolAddress((void**)&pt1, g_t1);
    float* pm;  cudaGetSymbolAddress((void**)&pm,  g_mask);

    cudaFuncSetAttribute(gemm_tf32_mma_kernel,
                         cudaFuncAttributeMaxDynamicSharedMemorySize, GEMM_MMA_SMEM);
    cudaFuncSetAttribute(flash_mma_kernel,
                         cudaFuncAttributeMaxDynamicSharedMemorySize, FLASH2_SMEM);

    const float scaling = 0.125f;   // 64^-0.5

    // q/k/v projections on TF32 mma.sync tensor cores
    dim3 gT(EMB / WBN, MROWS / WBM);            // 8 x 32
    gemm_tf32_mma_kernel<<<gT, 256, GEMM_MMA_SMEM>>>(query, q_w, q_b, pq, MROWS, EMB, EMB, scaling);
    gemm_tf32_mma_kernel<<<gT, 256, GEMM_MMA_SMEM>>>(query, k_w, k_b, pk, MROWS, EMB, EMB, 1.f);
    gemm_tf32_mma_kernel<<<gT, 256, GEMM_MMA_SMEM>>>(query, v_w, v_b, pv, MROWS, EMB, EMB, 1.f);

    // mask path stays exact fp32 (top-k threshold sensitivity)
    dim3 g1(MLP_H / BN, MROWS / BM);            // 4 x 32
    gemm_bias_kernel<<<g1, 256>>>(query, inf1_w, inf1_b, pt1, MROWS, MLP_H, EMB, 1.f, 1);
    mask_kernel<<<MROWS / 64, 256>>>(pt1, inf2_w, inf2_b, head_sig, pm);

    // flash attention on tensor cores
    dim3 gf(S_LEN / 128, HEADS, BATCH);         // 16 x 16 x 2
    flash_mma_kernel<<<gf, 256, FLASH2_SMEM>>>(pq, pk, pv, pm, po);

    // out projection on TF32 mma.sync
    gemm_tf32_mma_kernel<<<gT, 256, GEMM_MMA_SMEM>>>(po, out_w, out_b, out, MROWS, EMB, EMB, 1.f);
}

// round 5
// speedup vs baseline: 2.7229x; 1.1284x over previous
#include <cuda_runtime.h>
#include <cuda_bf16.h>
#include <cuda_fp16.h>
#include <cstdint>
#include <cstddef>

// Problem constants
#define S_LEN 2048
#define BATCH 2
#define EMB   1024
#define HEADS 16
#define HDIM  64
#define MROWS (S_LEN * BATCH)      // 4096
#define MLP_H 512
#define SIGD  64
#define KEEP  12                   // NUM_HEADS - INACTIVE

// ---------------- scratch (device globals; no allocation allowed) -------------
__device__ float g_q[MROWS * EMB];
__device__ float g_k[MROWS * EMB];
__device__ float g_v[MROWS * EMB];
__device__ float g_o[MROWS * EMB];
__device__ float g_t1[MROWS * MLP_H];
__device__ float g_mask[MROWS * HEADS];

// ======================= warp-level mma.sync helpers ==========================
__device__ __forceinline__ void mma_tf32(float* c, const uint32_t* a,
                                         uint32_t b0, uint32_t b1)
{
    asm volatile(
        "mma.sync.aligned.m16n8k8.row.col.f32.tf32.tf32.f32 "
        "{%0,%1,%2,%3}, {%4,%5,%6,%7}, {%8,%9}, {%0,%1,%2,%3};"
        : "+f"(c[0]), "+f"(c[1]), "+f"(c[2]), "+f"(c[3])
        : "r"(a[0]), "r"(a[1]), "r"(a[2]), "r"(a[3]), "r"(b0), "r"(b1));
}

__device__ __forceinline__ void mma_f16(float* c, const uint32_t* a,
                                        uint32_t b0, uint32_t b1)
{
    asm volatile(
        "mma.sync.aligned.m16n8k16.row.col.f32.f16.f16.f32 "
        "{%0,%1,%2,%3}, {%4,%5,%6,%7}, {%8,%9}, {%0,%1,%2,%3};"
        : "+f"(c[0]), "+f"(c[1]), "+f"(c[2]), "+f"(c[3])
        : "r"(a[0]), "r"(a[1]), "r"(a[2]), "r"(a[3]), "r"(b0), "r"(b1));
}

__device__ __forceinline__ uint32_t f2tf32(float f) {
    uint32_t u;
    asm("cvt.rna.tf32.f32 %0, %1;" : "=r"(u) : "f"(f));
    return u;
}
__device__ __forceinline__ uint4 cvt_tf32x4(float4 v) {
    uint4 u;
    u.x = f2tf32(v.x); u.y = f2tf32(v.y);
    u.z = f2tf32(v.z); u.w = f2tf32(v.w);
    return u;
}
__device__ __forceinline__ uint32_t pack_h2(__half a, __half b) {
    __half2 h = __halves2half2(a, b);
    return *(uint32_t*)&h;
}
// split a float4 (4 consecutive k) into hi/lo half2 pairs
__device__ __forceinline__ void split4(float4 v, uint2& hi, uint2& lo) {
    float f[4] = {v.x, v.y, v.z, v.w};
    __half hh[4], hl[4];
#pragma unroll
    for (int e = 0; e < 4; ++e) {
        hh[e] = __float2half_rn(f[e]);
        hl[e] = __float2half_rn(f[e] - __half2float(hh[e]));
    }
    hi = make_uint2(pack_h2(hh[0], hh[1]), pack_h2(hh[2], hh[3]));
    lo = make_uint2(pack_h2(hl[0], hl[1]), pack_h2(hl[2], hl[3]));
}

// ==============================================================================
// TF32 mma.sync GEMM: C = (A @ W^T + bias) * scale
// 128x128x32 tile, 256 threads, SINGLE-buffered smem + register prefetch
// -> 36.9KB smem -> 2 CTAs/SM.
// ==============================================================================
#define WBM 128
#define WBN 128
#define WBK 32
#define ASTR 36
#define TILE_WORDS (128 * ASTR)
#define GEMM_MMA_SMEM (2 * TILE_WORDS * 4)      // A + B = 36864 B

__global__ __launch_bounds__(256, 2) void gemm_tf32_mma_kernel(
    const float* __restrict__ A, const float* __restrict__ W,
    const float* __restrict__ bias, float* __restrict__ C,
    int M, int N, int K, float scale)
{
    extern __shared__ uint32_t smw[];
    uint32_t* Asm = smw;
    uint32_t* Bsm = smw + TILE_WORDS;

    const int tid  = threadIdx.x;
    const int lane = tid & 31;
    const int wid  = tid >> 5;
    const int wm   = wid & 3;
    const int wn   = wid >> 2;
    const int g    = lane >> 2;
    const int t    = lane & 3;
    const int m0   = blockIdx.y * WBM;
    const int n0   = blockIdx.x * WBN;
    const int NB   = K / WBK;

    const int lrow = tid >> 3;
    const int lc4  = (tid & 7) * 4;

    float c[2][8][4];
#pragma unroll
    for (int mf = 0; mf < 2; ++mf)
#pragma unroll
        for (int nf = 0; nf < 8; ++nf)
#pragma unroll
            for (int i = 0; i < 4; ++i) c[mf][nf][i] = 0.f;

    float4 ra[4], rb[4];
    auto load_regs = [&](int kk) {
#pragma unroll
        for (int p = 0; p < 4; ++p) {
            int row = lrow + p * 32;
            ra[p] = *(const float4*)&A[(size_t)(m0 + row) * K + kk + lc4];
            rb[p] = *(const float4*)&W[(size_t)(n0 + row) * K + kk + lc4];
        }
    };
    auto store_smem = [&]() {
#pragma unroll
        for (int p = 0; p < 4; ++p) {
            int row = lrow + p * 32;
            *(uint4*)&Asm[row * ASTR + lc4] = cvt_tf32x4(ra[p]);
            *(uint4*)&Bsm[row * ASTR + lc4] = cvt_tf32x4(rb[p]);
        }
    };

    load_regs(0);
    store_smem();
    __syncthreads();

    for (int kb = 0; kb < NB; ++kb) {
        const bool pre = (kb + 1 < NB);
        if (pre) load_regs((kb + 1) * WBK);

#pragma unroll
        for (int ks = 0; ks < 4; ++ks) {
            uint32_t a[2][4];
#pragma unroll
            for (int mf = 0; mf < 2; ++mf) {
                int r  = wm * 32 + mf * 16 + g;
                int cc = ks * 8 + t;
                a[mf][0] = Asm[r * ASTR + cc];
                a[mf][1] = Asm[(r + 8) * ASTR + cc];
                a[mf][2] = Asm[r * ASTR + cc + 4];
                a[mf][3] = Asm[(r + 8) * ASTR + cc + 4];
            }
#pragma unroll
            for (int nf = 0; nf < 8; ++nf) {
                int r  = wn * 64 + nf * 8 + g;
                int cc = ks * 8 + t;
                uint32_t b0 = Bsm[r * ASTR + cc];
                uint32_t b1 = Bsm[r * ASTR + cc + 4];
                mma_tf32(c[0][nf], a[0], b0, b1);
                mma_tf32(c[1][nf], a[1], b0, b1);
            }
        }
        __syncthreads();           // all warps done reading smem
        if (pre) {
            store_smem();
            __syncthreads();       // new block visible
        }
    }

#pragma unroll
    for (int mf = 0; mf < 2; ++mf) {
        int row0 = m0 + wm * 32 + mf * 16 + g;
#pragma unroll
        for (int nf = 0; nf < 8; ++nf) {
            int col = n0 + wn * 64 + nf * 8 + t * 2;
            float2 bv = *(const float2*)&bias[col];
            float2 r0, r1;
            r0.x = (c[mf][nf][0] + bv.x) * scale;
            r0.y = (c[mf][nf][1] + bv.y) * scale;
            r1.x = (c[mf][nf][2] + bv.x) * scale;
            r1.y = (c[mf][nf][3] + bv.y) * scale;
            *(float2*)&C[(size_t)row0 * N + col]       = r0;
            *(float2*)&C[(size_t)(row0 + 8) * N + col] = r1;
        }
    }
}

// ==============================================================================
// Split-fp16 GEMM (near-fp32 accuracy): C = relu?(A @ W^T + bias)
// 128x128x32 tile, 256 threads, single-buffered, 41KB smem -> 2 CTAs/SM.
// Used for the mask-path inf1 GEMM (top-k needs near-exact scores).
// ==============================================================================
#define HSTR 20                   // pair stride: 16 half2-pairs + 4 pad
#define HTILE (128 * HSTR)        // 2560 words per component
#define GEMM_F16S_SMEM (4 * HTILE * 4)   // Ah,Al,Wh,Wl = 40960 B

__global__ __launch_bounds__(256, 2) void gemm_f16split_kernel(
    const float* __restrict__ A, const float* __restrict__ W,
    const float* __restrict__ bias, float* __restrict__ C,
    int M, int N, int K, int relu)
{
    extern __shared__ uint32_t smh[];
    uint32_t* Ah = smh;
    uint32_t* Al = smh + HTILE;
    uint32_t* Wh = smh + 2 * HTILE;
    uint32_t* Wl = smh + 3 * HTILE;

    const int tid  = threadIdx.x;
    const int lane = tid & 31;
    const int wid  = tid >> 5;
    const int wm   = wid & 3;
    const int wn   = wid >> 2;
    const int g    = lane >> 2;
    const int t    = lane & 3;
    const int m0   = blockIdx.y * WBM;
    const int n0   = blockIdx.x * WBN;
    const int NB   = K / WBK;

    const int lrow = tid >> 3;          // 0..31
    const int lc4  = (tid & 7) * 4;     // k-col base (floats)
    const int lpr  = (tid & 7) * 2;     // pair base

    float c[2][8][4];
#pragma unroll
    for (int mf = 0; mf < 2; ++mf)
#pragma unroll
        for (int nf = 0; nf < 8; ++nf)
#pragma unroll
            for (int i = 0; i < 4; ++i) c[mf][nf][i] = 0.f;

    float4 ra[4], rb[4];
    auto load_regs = [&](int kk) {
#pragma unroll
        for (int p = 0; p < 4; ++p) {
            int row = lrow + p * 32;
            ra[p] = *(const float4*)&A[(size_t)(m0 + row) * K + kk + lc4];
            rb[p] = *(const float4*)&W[(size_t)(n0 + row) * K + kk + lc4];
        }
    };
    auto store_smem = [&]() {
#pragma unroll
        for (int p = 0; p < 4; ++p) {
            int row = lrow + p * 32;
            uint2 hi, lo;
            split4(ra[p], hi, lo);
            *(uint2*)&Ah[row * HSTR + lpr] = hi;
            *(uint2*)&Al[row * HSTR + lpr] = lo;
            split4(rb[p], hi, lo);
            *(uint2*)&Wh[row * HSTR + lpr] = hi;
            *(uint2*)&Wl[row * HSTR + lpr] = lo;
        }
    };

    load_regs(0);
    store_smem();
    __syncthreads();

    for (int kb = 0; kb < NB; ++kb) {
        const bool pre = (kb + 1 < NB);
        if (pre) load_regs((kb + 1) * WBK);

#pragma unroll
        for (int ks = 0; ks < 2; ++ks) {           // 2 x k16
            uint32_t ah[2][4], al[2][4];
#pragma unroll
            for (int mf = 0; mf < 2; ++mf) {
                int r  = wm * 32 + mf * 16 + g;
                int cc = ks * 8 + t;
                ah[mf][0] = Ah[r * HSTR + cc];
                ah[mf][1] = Ah[(r + 8) * HSTR + cc];
                ah[mf][2] = Ah[r * HSTR + cc + 4];
                ah[mf][3] = Ah[(r + 8) * HSTR + cc + 4];
                al[mf][0] = Al[r * HSTR + cc];
                al[mf][1] = Al[(r + 8) * HSTR + cc];
                al[mf][2] = Al[r * HSTR + cc + 4];
                al[mf][3] = Al[(r + 8) * HSTR + cc + 4];
            }
#pragma unroll
            for (int nf = 0; nf < 8; ++nf) {
                int r  = wn * 64 + nf * 8 + g;
                int cc = ks * 8 + t;
                uint32_t bh0 = Wh[r * HSTR + cc];
                uint32_t bh1 = Wh[r * HSTR + cc + 4];
                uint32_t bl0 = Wl[r * HSTR + cc];
                uint32_t bl1 = Wl[r * HSTR + cc + 4];
#pragma unroll
                for (int mf = 0; mf < 2; ++mf) {
                    mma_f16(c[mf][nf], ah[mf], bh0, bh1);
                    mma_f16(c[mf][nf], al[mf], bh0, bh1);
                    mma_f16(c[mf][nf], ah[mf], bl0, bl1);
                }
            }
        }
        __syncthreads();
        if (pre) {
            store_smem();
            __syncthreads();
        }
    }

#pragma unroll
    for (int mf = 0; mf < 2; ++mf) {
        int row0 = m0 + wm * 32 + mf * 16 + g;
#pragma unroll
        for (int nf = 0; nf < 8; ++nf) {
            int col = n0 + wn * 64 + nf * 8 + t * 2;
            float2 bv = *(const float2*)&bias[col];
            float2 r0, r1;
            r0.x = c[mf][nf][0] + bv.x;
            r0.y = c[mf][nf][1] + bv.y;
            r1.x = c[mf][nf][2] + bv.x;
            r1.y = c[mf][nf][3] + bv.y;
            if (relu) {
                r0.x = fmaxf(r0.x, 0.f); r0.y = fmaxf(r0.y, 0.f);
                r1.x = fmaxf(r1.x, 0.f); r1.y = fmaxf(r1.y, 0.f);
            }
            *(float2*)&C[(size_t)row0 * N + col]       = r0;
            *(float2*)&C[(size_t)(row0 + 8) * N + col] = r1;
        }
    }
}

// ==============================================================================
// Mask kernel (fp32 exact)
// ==============================================================================
__global__ __launch_bounds__(256) void mask_kernel(
    const float* __restrict__ T1, const float* __restrict__ W2,
    const float* __restrict__ b2, const float* __restrict__ HS,
    float* __restrict__ maskOut)
{
    __shared__ float As[16][68];
    __shared__ float Ws[16][68];
    __shared__ float T2[64][68];
    __shared__ float HSs[16][68];
    __shared__ float Sc[64][16];

    const int tid = threadIdx.x;
    const int tx = tid & 15;
    const int ty = tid >> 4;
    const int m0 = blockIdx.x * 64;

    {
        int hrow = tid >> 4;
        int c4   = (tid & 15) * 4;
        float4 v = *(const float4*)&HS[(size_t)hrow * 64 + c4];
        *(float4*)&HSs[hrow][c4] = v;
    }

    float acc[4][4];
#pragma unroll
    for (int i = 0; i < 4; ++i)
#pragma unroll
        for (int j = 0; j < 4; ++j) acc[i][j] = 0.f;

    const int row = tid >> 2;
    const int kc  = (tid & 3) * 4;

    for (int kk = 0; kk < MLP_H; kk += 16) {
        float4 a = *(const float4*)&T1[(size_t)(m0 + row) * MLP_H + kk + kc];
        As[kc + 0][row] = a.x; As[kc + 1][row] = a.y;
        As[kc + 2][row] = a.z; As[kc + 3][row] = a.w;
        float4 w = *(const float4*)&W2[(size_t)row * MLP_H + kk + kc];
        Ws[kc + 0][row] = w.x; Ws[kc + 1][row] = w.y;
        Ws[kc + 2][row] = w.z; Ws[kc + 3][row] = w.w;
        __syncthreads();
#pragma unroll
        for (int k = 0; k < 16; ++k) {
            float a4[4], b4[4];
            *(float4*)&a4[0] = *(const float4*)&As[k][ty * 4];
            *(float4*)&b4[0] = *(const float4*)&Ws[k][tx * 4];
#pragma unroll
            for (int i = 0; i < 4; ++i)
#pragma unroll
                for (int j = 0; j < 4; ++j)
                    acc[i][j] = fmaf(a4[i], b4[j], acc[i][j]);
        }
        __syncthreads();
    }

#pragma unroll
    for (int i = 0; i < 4; ++i)
#pragma unroll
        for (int j = 0; j < 4; ++j)
            T2[ty * 4 + i][tx * 4 + j] = acc[i][j] + b2[tx * 4 + j];
    __syncthreads();

    {
        int r  = tid >> 2;
        int hg = (tid & 3) * 4;
        float sc[4] = {0.f, 0.f, 0.f, 0.f};
#pragma unroll 8
        for (int d = 0; d < 64; ++d) {
            float tv = T2[r][d];
            sc[0] = fmaf(tv, HSs[hg + 0][d], sc[0]);
            sc[1] = fmaf(tv, HSs[hg + 1][d], sc[1]);
            sc[2] = fmaf(tv, HSs[hg + 2][d], sc[2]);
            sc[3] = fmaf(tv, HSs[hg + 3][d], sc[3]);
        }
        *(float4*)&Sc[r][hg] = make_float4(sc[0], sc[1], sc[2], sc[3]);
    }
    __syncthreads();

    if (tid < 64) {
        float vals[16];
#pragma unroll
        for (int h = 0; h < 16; ++h) vals[h] = Sc[tid][h];
        bool used[16];
#pragma unroll
        for (int h = 0; h < 16; ++h) used[h] = false;
        float kth = -1e30f;
        for (int it = 0; it < KEEP; ++it) {
            float mx = -1e30f; int mi = 0;
            for (int h = 0; h < 16; ++h)
                if (!used[h] && vals[h] > mx) { mx = vals[h]; mi = h; }
            used[mi] = true;
            kth = mx;
        }
        for (int h = 0; h < 16; ++h)
            maskOut[(size_t)(m0 + tid) * HEADS + h] = (vals[h] >= kth) ? 1.f : 0.f;
    }
}

// ==============================================================================
// Flash attention on tensor cores (unchanged from R4 passing version).
// QK^T: split fp16 (3-term).  P*V: single TF32.
// ==============================================================================
#define KST2 36
#define VST  72
#define PST  68

#define OFF_KSH 0
#define OFF_KSL (2 * 64 * KST2)
#define OFF_VS  (OFF_KSL + 2 * 64 * KST2)
#define OFF_PS  (OFF_VS + 2 * 64 * VST)
#define FLASH2_WORDS (OFF_PS + 128 * PST)
#define FLASH2_SMEM (FLASH2_WORDS * 4)   // 108544 B

__global__ __launch_bounds__(256, 1) void flash_mma_kernel(
    const float* __restrict__ Qg, const float* __restrict__ Kg,
    const float* __restrict__ Vg, const float* __restrict__ maskp,
    float* __restrict__ Og)
{
    extern __shared__ uint32_t smf[];
    uint32_t* Ksh = smf + OFF_KSH;
    uint32_t* Ksl = smf + OFF_KSL;
    uint32_t* Vss = smf + OFF_VS;
    uint32_t* Pss = smf + OFF_PS;

    const int tid  = threadIdx.x;
    const int lane = tid & 31;
    const int wid  = tid >> 5;
    const int g    = lane >> 2;
    const int t    = lane & 3;
    const int mbase = wid * 16;

    const int qt = blockIdx.x;
    const int h  = blockIdx.y;
    const int b  = blockIdx.z;
    const int s0 = qt * 128;
    const size_t rowstride = (size_t)BATCH * EMB;
    const size_t cbase = (size_t)b * EMB + (size_t)h * HDIM;

    float* Qst = (float*)Pss;
#pragma unroll
    for (int p = 0; p < 8; ++p) {
        int idx = tid + p * 256;
        int row = idx >> 4;
        int c4  = (idx & 15) * 4;
        float4 v = *(const float4*)&Qg[(size_t)(s0 + row) * rowstride + cbase + c4];
        *(float4*)&Qst[row * PST + c4] = v;
    }
    __syncthreads();

    uint32_t qh[4][4], ql[4][4];
#pragma unroll
    for (int ks = 0; ks < 4; ++ks) {
        int r0 = mbase + g, r1 = mbase + g + 8;
        int c0 = ks * 16 + 2 * t;
#pragma unroll
        for (int fi = 0; fi < 4; ++fi) {
            int rr = (fi & 1) ? r1 : r0;
            int cc = c0 + ((fi >> 1) ? 8 : 0);
            float f0 = Qst[rr * PST + cc];
            float f1 = Qst[rr * PST + cc + 1];
            __half h0 = __float2half_rn(f0);
            __half h1 = __float2half_rn(f1);
            __half l0 = __float2half_rn(f0 - __half2float(h0));
            __half l1 = __float2half_rn(f1 - __half2float(h1));
            qh[ks][fi] = pack_h2(h0, h1);
            ql[ks][fi] = pack_h2(l0, l1);
        }
    }

    const int lrow = tid >> 4;
    const int lc4  = (tid & 15) * 4;
    float4 kr[4], vr[4];

    auto load_kv = [&](int kt) {
#pragma unroll
        for (int p = 0; p < 4; ++p) {
            int row = lrow + p * 16;
            size_t goff = (size_t)(kt * 64 + row) * rowstride + cbase + lc4;
            kr[p] = *(const float4*)&Kg[goff];
            vr[p] = *(const float4*)&Vg[goff];
        }
    };
    auto store_kv = [&](int bb) {
        uint32_t* Kh = Ksh + bb * 64 * KST2;
        uint32_t* Kl = Ksl + bb * 64 * KST2;
        uint32_t* Vb = Vss + bb * 64 * VST;
#pragma unroll
        for (int p = 0; p < 4; ++p) {
            int row = lrow + p * 16;
            float f[4] = {kr[p].x, kr[p].y, kr[p].z, kr[p].w};
            __half hh[4], hl[4];
#pragma unroll
            for (int e = 0; e < 4; ++e) {
                hh[e] = __float2half_rn(f[e]);
                hl[e] = __float2half_rn(f[e] - __half2float(hh[e]));
            }
            int pr = (tid & 15) * 2;
            Kh[row * KST2 + pr]     = pack_h2(hh[0], hh[1]);
            Kh[row * KST2 + pr + 1] = pack_h2(hh[2], hh[3]);
            Kl[row * KST2 + pr]     = pack_h2(hl[0], hl[1]);
            Kl[row * KST2 + pr + 1] = pack_h2(hl[2], hl[3]);
            *(uint4*)&Vb[row * VST + lc4] = cvt_tf32x4(vr[p]);
        }
    };

    load_kv(0);
    store_kv(0);
    __syncthreads();

    float o[8][4];
    float m0r = -1e30f, m1r = -1e30f, l0r = 0.f, l1r = 0.f;
#pragma unroll
    for (int nf = 0; nf < 8; ++nf)
#pragma unroll
        for (int i = 0; i < 4; ++i) o[nf][i] = 0.f;

    const int NKT = S_LEN / 64;
    for (int kt = 0; kt < NKT; ++kt) {
        const int bb = kt & 1;
        const uint32_t* Kh = Ksh + bb * 64 * KST2;
        const uint32_t* Kl = Ksl + bb * 64 * KST2;
        const uint32_t* Vb = Vss + bb * 64 * VST;

        float sc[8][4];
#pragma unroll
        for (int nf = 0; nf < 8; ++nf)
#pragma unroll
            for (int i = 0; i < 4; ++i) sc[nf][i] = 0.f;

#pragma unroll
        for (int ks = 0; ks < 4; ++ks) {
#pragma unroll
            for (int nf = 0; nf < 8; ++nf) {
                int krow = nf * 8 + g;
                uint32_t b0h = Kh[krow * KST2 + ks * 8 + t];
                uint32_t b1h = Kh[krow * KST2 + ks * 8 + t + 4];
                uint32_t b0l = Kl[krow * KST2 + ks * 8 + t];
                uint32_t b1l = Kl[krow * KST2 + ks * 8 + t + 4];
                mma_f16(sc[nf], qh[ks], b0h, b1h);
                mma_f16(sc[nf], ql[ks], b0h, b1h);
                mma_f16(sc[nf], qh[ks], b0l, b1l);
            }
        }

        if (kt + 1 < NKT) load_kv(kt + 1);

        float tm0 = -1e30f, tm1 = -1e30f;
#pragma unroll
        for (int nf = 0; nf < 8; ++nf) {
            tm0 = fmaxf(tm0, fmaxf(sc[nf][0], sc[nf][1]));
            tm1 = fmaxf(tm1, fmaxf(sc[nf][2], sc[nf][3]));
        }
        tm0 = fmaxf(tm0, __shfl_xor_sync(0xffffffffu, tm0, 1));
        tm0 = fmaxf(tm0, __shfl_xor_sync(0xffffffffu, tm0, 2));
        tm1 = fmaxf(tm1, __shfl_xor_sync(0xffffffffu, tm1, 1));
        tm1 = fmaxf(tm1, __shfl_xor_sync(0xffffffffu, tm1, 2));

        float mn0 = fmaxf(m0r, tm0);
        float mn1 = fmaxf(m1r, tm1);
        float al0 = __expf(m0r - mn0);
        float al1 = __expf(m1r - mn1);

        float ls0 = 0.f, ls1 = 0.f;
#pragma unroll
        for (int nf = 0; nf < 8; ++nf) {
            sc[nf][0] = __expf(sc[nf][0] - mn0);
            sc[nf][1] = __expf(sc[nf][1] - mn0);
            sc[nf][2] = __expf(sc[nf][2] - mn1);
            sc[nf][3] = __expf(sc[nf][3] - mn1);
            ls0 += sc[nf][0] + sc[nf][1];
            ls1 += sc[nf][2] + sc[nf][3];
        }
        ls0 += __shfl_xor_sync(0xffffffffu, ls0, 1);
        ls0 += __shfl_xor_sync(0xffffffffu, ls0, 2);
        ls1 += __shfl_xor_sync(0xffffffffu, ls1, 1);
        ls1 += __shfl_xor_sync(0xffffffffu, ls1, 2);

        l0r = l0r * al0 + ls0;  m0r = mn0;
        l1r = l1r * al1 + ls1;  m1r = mn1;

#pragma unroll
        for (int nf = 0; nf < 8; ++nf) {
            o[nf][0] *= al0; o[nf][1] *= al0;
            o[nf][2] *= al1; o[nf][3] *= al1;
        }

#pragma unroll
        for (int nf = 0; nf < 8; ++nf) {
            int col = nf * 8 + 2 * t;
            uint2 p0 = make_uint2(f2tf32(sc[nf][0]), f2tf32(sc[nf][1]));
            uint2 p1 = make_uint2(f2tf32(sc[nf][2]), f2tf32(sc[nf][3]));
            *(uint2*)&Pss[(mbase + g) * PST + col]     = p0;
            *(uint2*)&Pss[(mbase + g + 8) * PST + col] = p1;
        }

        if (kt + 1 < NKT) store_kv(bb ^ 1);

        __syncthreads();

#pragma unroll
        for (int ks = 0; ks < 8; ++ks) {
            uint32_t a[4];
            a[0] = Pss[(mbase + g) * PST + ks * 8 + t];
            a[1] = Pss[(mbase + g + 8) * PST + ks * 8 + t];
            a[2] = Pss[(mbase + g) * PST + ks * 8 + t + 4];
            a[3] = Pss[(mbase + g + 8) * PST + ks * 8 + t + 4];
#pragma unroll
            for (int nf = 0; nf < 8; ++nf) {
                uint32_t b0 = Vb[(ks * 8 + t) * VST + nf * 8 + g];
                uint32_t b1 = Vb[(ks * 8 + t + 4) * VST + nf * 8 + g];
                mma_tf32(o[nf], a, b0, b1);
            }
        }
        __syncthreads();
    }

    int srow0 = s0 + mbase + g;
    int srow1 = srow0 + 8;
    float mv0 = maskp[((size_t)srow0 * BATCH + b) * HEADS + h];
    float mv1 = maskp[((size_t)srow1 * BATCH + b) * HEADS + h];
    float inv0 = mv0 / l0r;
    float inv1 = mv1 / l1r;
#pragma unroll
    for (int nf = 0; nf < 8; ++nf) {
        int col = nf * 8 + 2 * t;
        float2 r0 = make_float2(o[nf][0] * inv0, o[nf][1] * inv0);
        float2 r1 = make_float2(o[nf][2] * inv1, o[nf][3] * inv1);
        *(float2*)&Og[(size_t)srow0 * rowstride + cbase + col] = r0;
        *(float2*)&Og[(size_t)srow1 * rowstride + cbase + col] = r1;
    }
}

// ==============================================================================
// launch
// ==============================================================================
extern "C" void kernel_launch(void* const* d_in, const int* in_sizes, int n_in,
                              void* d_out, int out_size)
{
    (void)in_sizes; (void)n_in; (void)out_size;
    const float* query   = (const float*)d_in[0];
    const float* q_w     = (const float*)d_in[1];
    const float* q_b     = (const float*)d_in[2];
    const float* k_w     = (const float*)d_in[3];
    const float* k_b     = (const float*)d_in[4];
    const float* v_w     = (const float*)d_in[5];
    const float* v_b     = (const float*)d_in[6];
    const float* out_w   = (const float*)d_in[7];
    const float* out_b   = (const float*)d_in[8];
    const float* inf1_w  = (const float*)d_in[9];
    const float* inf1_b  = (const float*)d_in[10];
    const float* inf2_w  = (const float*)d_in[11];
    const float* inf2_b  = (const float*)d_in[12];
    const float* head_sig= (const float*)d_in[13];
    float* out = (float*)d_out;

    float* pq;  cudaGetSymbolAddress((void**)&pq,  g_q);
    float* pk;  cudaGetSymbolAddress((void**)&pk,  g_k);
    float* pv;  cudaGetSymbolAddress((void**)&pv,  g_v);
    float* po;  cudaGetSymbolAddress((void**)&po,  g_o);
    float* pt1; cudaGetSymbolAddress((void**)&pt1, g_t1);
    float* pm;  cudaGetSymbolAddress((void**)&pm,  g_mask);

    cudaFuncSetAttribute(gemm_tf32_mma_kernel,
                         cudaFuncAttributeMaxDynamicSharedMemorySize, GEMM_MMA_SMEM);
    cudaFuncSetAttribute(gemm_f16split_kernel,
                         cudaFuncAttributeMaxDynamicSharedMemorySize, GEMM_F16S_SMEM);
    cudaFuncSetAttribute(flash_mma_kernel,
                         cudaFuncAttributeMaxDynamicSharedMemorySize, FLASH2_SMEM);

    const float scaling = 0.125f;   // 64^-0.5

    // q/k/v projections on TF32 mma.sync tensor cores (2 CTAs/SM now)
    dim3 gT(EMB / WBN, MROWS / WBM);            // 8 x 32
    gemm_tf32_mma_kernel<<<gT, 256, GEMM_MMA_SMEM>>>(query, q_w, q_b, pq, MROWS, EMB, EMB, scaling);
    gemm_tf32_mma_kernel<<<gT, 256, GEMM_MMA_SMEM>>>(query, k_w, k_b, pk, MROWS, EMB, EMB, 1.f);
    gemm_tf32_mma_kernel<<<gT, 256, GEMM_MMA_SMEM>>>(query, v_w, v_b, pv, MROWS, EMB, EMB, 1.f);

    // mask path: inf1 on split-fp16 tensor cores (near-fp32 exact), rest fp32
    dim3 g1(MLP_H / WBN, MROWS / WBM);          // 4 x 32
    gemm_f16split_kernel<<<g1, 256, GEMM_F16S_SMEM>>>(query, inf1_w, inf1_b, pt1, MROWS, MLP_H, EMB, 1);
    mask_kernel<<<MROWS / 64, 256>>>(pt1, inf2_w, inf2_b, head_sig, pm);

    // flash attention on tensor cores
    dim3 gf(S_LEN / 128, HEADS, BATCH);         // 16 x 16 x 2
    flash_mma_kernel<<<gf, 256, FLASH2_SMEM>>>(pq, pk, pv, pm, po);

    // out projection on TF32 mma.sync
    gemm_tf32_mma_kernel<<<gT, 256, GEMM_MMA_SMEM>>>(po, out_w, out_b, out, MROWS, EMB, EMB, 1.f);
}

// round 6
// speedup vs baseline: 3.0818x; 1.1318x over previous
#include <cuda_runtime.h>
#include <cuda_bf16.h>
#include <cuda_fp16.h>
#include <cstdint>
#include <cstddef>

// Problem constants
#define S_LEN 2048
#define BATCH 2
#define EMB   1024
#define HEADS 16
#define HDIM  64
#define MROWS (S_LEN * BATCH)      // 4096
#define MLP_H 512
#define SIGD  64
#define KEEP  12                   // NUM_HEADS - INACTIVE

// ---------------- scratch (device globals; no allocation allowed) -------------
__device__ float g_q[MROWS * EMB];
__device__ float g_k[MROWS * EMB];
__device__ float g_v[MROWS * EMB];
__device__ float g_o[MROWS * EMB];
__device__ float g_t1[MROWS * MLP_H];
__device__ float g_mask[MROWS * HEADS];

// ======================= warp-level mma.sync helpers ==========================
__device__ __forceinline__ void mma_tf32(float* c, const uint32_t* a,
                                         uint32_t b0, uint32_t b1)
{
    asm volatile(
        "mma.sync.aligned.m16n8k8.row.col.f32.tf32.tf32.f32 "
        "{%0,%1,%2,%3}, {%4,%5,%6,%7}, {%8,%9}, {%0,%1,%2,%3};"
        : "+f"(c[0]), "+f"(c[1]), "+f"(c[2]), "+f"(c[3])
        : "r"(a[0]), "r"(a[1]), "r"(a[2]), "r"(a[3]), "r"(b0), "r"(b1));
}

__device__ __forceinline__ void mma_f16(float* c, const uint32_t* a,
                                        uint32_t b0, uint32_t b1)
{
    asm volatile(
        "mma.sync.aligned.m16n8k16.row.col.f32.f16.f16.f32 "
        "{%0,%1,%2,%3}, {%4,%5,%6,%7}, {%8,%9}, {%0,%1,%2,%3};"
        : "+f"(c[0]), "+f"(c[1]), "+f"(c[2]), "+f"(c[3])
        : "r"(a[0]), "r"(a[1]), "r"(a[2]), "r"(a[3]), "r"(b0), "r"(b1));
}

__device__ __forceinline__ void ldsm_x4(uint32_t* r, uint32_t addr) {
    asm volatile(
        "ldmatrix.sync.aligned.m8n8.x4.shared.b16 {%0,%1,%2,%3}, [%4];"
        : "=r"(r[0]), "=r"(r[1]), "=r"(r[2]), "=r"(r[3]) : "r"(addr));
}
__device__ __forceinline__ void ldsm_x4_t(uint32_t* r, uint32_t addr) {
    asm volatile(
        "ldmatrix.sync.aligned.m8n8.x4.trans.shared.b16 {%0,%1,%2,%3}, [%4];"
        : "=r"(r[0]), "=r"(r[1]), "=r"(r[2]), "=r"(r[3]) : "r"(addr));
}

__device__ __forceinline__ uint32_t smem_to_u32(const void* smem_ptr) {
    uint32_t addr;
    asm("{ .reg .u64 tmp; cvta.to.shared.u64 tmp, %1; cvt.u32.u64 %0, tmp; }"
        : "=r"(addr) : "l"(smem_ptr));
    return addr;
}

__device__ __forceinline__ uint32_t f2tf32(float f) {
    uint32_t u;
    asm("cvt.rna.tf32.f32 %0, %1;" : "=r"(u) : "f"(f));
    return u;
}
__device__ __forceinline__ uint4 cvt_tf32x4(float4 v) {
    uint4 u;
    u.x = f2tf32(v.x); u.y = f2tf32(v.y);
    u.z = f2tf32(v.z); u.w = f2tf32(v.w);
    return u;
}
__device__ __forceinline__ uint32_t pack_h2(__half a, __half b) {
    __half2 h = __halves2half2(a, b);
    return *(uint32_t*)&h;
}
__device__ __forceinline__ uint32_t pack_f2h2(float a, float b) {
    return pack_h2(__float2half_rn(a), __float2half_rn(b));
}
// split a float4 (4 consecutive elements) into hi/lo half pairs
__device__ __forceinline__ void split4(float4 v, uint2& hi, uint2& lo) {
    float f[4] = {v.x, v.y, v.z, v.w};
    __half hh[4], hl[4];
#pragma unroll
    for (int e = 0; e < 4; ++e) {
        hh[e] = __float2half_rn(f[e]);
        hl[e] = __float2half_rn(f[e] - __half2float(hh[e]));
    }
    hi = make_uint2(pack_h2(hh[0], hh[1]), pack_h2(hh[2], hh[3]));
    lo = make_uint2(pack_h2(hl[0], hl[1]), pack_h2(hl[2], hl[3]));
}

// ==============================================================================
// TF32 mma.sync GEMM: C = (A @ W^T + bias) * scale
// 128x128x32 tile, 256 threads, DOUBLE-buffered smem (one sync per k-block),
// 73.7KB smem, 2 CTAs/SM.
// ==============================================================================
#define WBM 128
#define WBN 128
#define WBK 32
#define ASTR 36
#define TILE_WORDS (128 * ASTR)
#define GEMM_MMA_SMEM (4 * TILE_WORDS * 4)      // A0,B0,A1,B1 = 73728 B

__global__ __launch_bounds__(256, 2) void gemm_tf32_mma_kernel(
    const float* __restrict__ A, const float* __restrict__ W,
    const float* __restrict__ bias, float* __restrict__ C,
    int M, int N, int K, float scale)
{
    extern __shared__ uint32_t smw[];

    const int tid  = threadIdx.x;
    const int lane = tid & 31;
    const int wid  = tid >> 5;
    const int wm   = wid & 3;
    const int wn   = wid >> 2;
    const int g    = lane >> 2;
    const int t    = lane & 3;
    const int m0   = blockIdx.y * WBM;
    const int n0   = blockIdx.x * WBN;
    const int NB   = K / WBK;

    const int lrow = tid >> 3;
    const int lc4  = (tid & 7) * 4;

    float c[2][8][4];
#pragma unroll
    for (int mf = 0; mf < 2; ++mf)
#pragma unroll
        for (int nf = 0; nf < 8; ++nf)
#pragma unroll
            for (int i = 0; i < 4; ++i) c[mf][nf][i] = 0.f;

    float4 ra[4], rb[4];
    auto load_regs = [&](int kk) {
#pragma unroll
        for (int p = 0; p < 4; ++p) {
            int row = lrow + p * 32;
            ra[p] = *(const float4*)&A[(size_t)(m0 + row) * K + kk + lc4];
            rb[p] = *(const float4*)&W[(size_t)(n0 + row) * K + kk + lc4];
        }
    };
    auto store_smem = [&](int buf) {
        uint32_t* Asm = smw + buf * 2 * TILE_WORDS;
        uint32_t* Bsm = Asm + TILE_WORDS;
#pragma unroll
        for (int p = 0; p < 4; ++p) {
            int row = lrow + p * 32;
            *(uint4*)&Asm[row * ASTR + lc4] = cvt_tf32x4(ra[p]);
            *(uint4*)&Bsm[row * ASTR + lc4] = cvt_tf32x4(rb[p]);
        }
    };

    load_regs(0);
    store_smem(0);
    __syncthreads();

    for (int kb = 0; kb < NB; ++kb) {
        const int b = kb & 1;
        const uint32_t* Asm = smw + b * 2 * TILE_WORDS;
        const uint32_t* Bsm = Asm + TILE_WORDS;
        const bool pre = (kb + 1 < NB);
        if (pre) load_regs((kb + 1) * WBK);

#pragma unroll
        for (int ks = 0; ks < 4; ++ks) {
            uint32_t a[2][4];
#pragma unroll
            for (int mf = 0; mf < 2; ++mf) {
                int r  = wm * 32 + mf * 16 + g;
                int cc = ks * 8 + t;
                a[mf][0] = Asm[r * ASTR + cc];
                a[mf][1] = Asm[(r + 8) * ASTR + cc];
                a[mf][2] = Asm[r * ASTR + cc + 4];
                a[mf][3] = Asm[(r + 8) * ASTR + cc + 4];
            }
#pragma unroll
            for (int nf = 0; nf < 8; ++nf) {
                int r  = wn * 64 + nf * 8 + g;
                int cc = ks * 8 + t;
                uint32_t b0 = Bsm[r * ASTR + cc];
                uint32_t b1 = Bsm[r * ASTR + cc + 4];
                mma_tf32(c[0][nf], a[0], b0, b1);
                mma_tf32(c[1][nf], a[1], b0, b1);
            }
        }
        if (pre) store_smem(b ^ 1);
        __syncthreads();
    }

#pragma unroll
    for (int mf = 0; mf < 2; ++mf) {
        int row0 = m0 + wm * 32 + mf * 16 + g;
#pragma unroll
        for (int nf = 0; nf < 8; ++nf) {
            int col = n0 + wn * 64 + nf * 8 + t * 2;
            float2 bv = *(const float2*)&bias[col];
            float2 r0, r1;
            r0.x = (c[mf][nf][0] + bv.x) * scale;
            r0.y = (c[mf][nf][1] + bv.y) * scale;
            r1.x = (c[mf][nf][2] + bv.x) * scale;
            r1.y = (c[mf][nf][3] + bv.y) * scale;
            *(float2*)&C[(size_t)row0 * N + col]       = r0;
            *(float2*)&C[(size_t)(row0 + 8) * N + col] = r1;
        }
    }
}

// ==============================================================================
// Split-fp16 GEMM (near-fp32): C = relu?(A @ W^T + bias)
// Double-buffered, 80KB smem, 2 CTAs/SM. Mask-path inf1.
// ==============================================================================
#define HSTR 20
#define HTILE (128 * HSTR)
#define GEMM_F16S_SMEM (8 * HTILE * 4)   // 2 bufs x (Ah,Al,Wh,Wl) = 81920 B

__global__ __launch_bounds__(256, 2) void gemm_f16split_kernel(
    const float* __restrict__ A, const float* __restrict__ W,
    const float* __restrict__ bias, float* __restrict__ C,
    int M, int N, int K, int relu)
{
    extern __shared__ uint32_t smh[];

    const int tid  = threadIdx.x;
    const int lane = tid & 31;
    const int wid  = tid >> 5;
    const int wm   = wid & 3;
    const int wn   = wid >> 2;
    const int g    = lane >> 2;
    const int t    = lane & 3;
    const int m0   = blockIdx.y * WBM;
    const int n0   = blockIdx.x * WBN;
    const int NB   = K / WBK;

    const int lrow = tid >> 3;
    const int lc4  = (tid & 7) * 4;
    const int lpr  = (tid & 7) * 2;

    float c[2][8][4];
#pragma unroll
    for (int mf = 0; mf < 2; ++mf)
#pragma unroll
        for (int nf = 0; nf < 8; ++nf)
#pragma unroll
            for (int i = 0; i < 4; ++i) c[mf][nf][i] = 0.f;

    float4 ra[4], rb[4];
    auto load_regs = [&](int kk) {
#pragma unroll
        for (int p = 0; p < 4; ++p) {
            int row = lrow + p * 32;
            ra[p] = *(const float4*)&A[(size_t)(m0 + row) * K + kk + lc4];
            rb[p] = *(const float4*)&W[(size_t)(n0 + row) * K + kk + lc4];
        }
    };
    auto store_smem = [&](int buf) {
        uint32_t* Ah = smh + buf * 4 * HTILE;
        uint32_t* Al = Ah + HTILE;
        uint32_t* Wh = Ah + 2 * HTILE;
        uint32_t* Wl = Ah + 3 * HTILE;
#pragma unroll
        for (int p = 0; p < 4; ++p) {
            int row = lrow + p * 32;
            uint2 hi, lo;
            split4(ra[p], hi, lo);
            *(uint2*)&Ah[row * HSTR + lpr] = hi;
            *(uint2*)&Al[row * HSTR + lpr] = lo;
            split4(rb[p], hi, lo);
            *(uint2*)&Wh[row * HSTR + lpr] = hi;
            *(uint2*)&Wl[row * HSTR + lpr] = lo;
        }
    };

    load_regs(0);
    store_smem(0);
    __syncthreads();

    for (int kb = 0; kb < NB; ++kb) {
        const int b = kb & 1;
        const uint32_t* Ah = smh + b * 4 * HTILE;
        const uint32_t* Al = Ah + HTILE;
        const uint32_t* Wh = Ah + 2 * HTILE;
        const uint32_t* Wl = Ah + 3 * HTILE;
        const bool pre = (kb + 1 < NB);
        if (pre) load_regs((kb + 1) * WBK);

#pragma unroll
        for (int ks = 0; ks < 2; ++ks) {
            uint32_t ah[2][4], al[2][4];
#pragma unroll
            for (int mf = 0; mf < 2; ++mf) {
                int r  = wm * 32 + mf * 16 + g;
                int cc = ks * 8 + t;
                ah[mf][0] = Ah[r * HSTR + cc];
                ah[mf][1] = Ah[(r + 8) * HSTR + cc];
                ah[mf][2] = Ah[r * HSTR + cc + 4];
                ah[mf][3] = Ah[(r + 8) * HSTR + cc + 4];
                al[mf][0] = Al[r * HSTR + cc];
                al[mf][1] = Al[(r + 8) * HSTR + cc];
                al[mf][2] = Al[r * HSTR + cc + 4];
                al[mf][3] = Al[(r + 8) * HSTR + cc + 4];
            }
#pragma unroll
            for (int nf = 0; nf < 8; ++nf) {
                int r  = wn * 64 + nf * 8 + g;
                int cc = ks * 8 + t;
                uint32_t bh0 = Wh[r * HSTR + cc];
                uint32_t bh1 = Wh[r * HSTR + cc + 4];
                uint32_t bl0 = Wl[r * HSTR + cc];
                uint32_t bl1 = Wl[r * HSTR + cc + 4];
#pragma unroll
                for (int mf = 0; mf < 2; ++mf) {
                    mma_f16(c[mf][nf], ah[mf], bh0, bh1);
                    mma_f16(c[mf][nf], al[mf], bh0, bh1);
                    mma_f16(c[mf][nf], ah[mf], bl0, bl1);
                }
            }
        }
        if (pre) store_smem(b ^ 1);
        __syncthreads();
    }

#pragma unroll
    for (int mf = 0; mf < 2; ++mf) {
        int row0 = m0 + wm * 32 + mf * 16 + g;
#pragma unroll
        for (int nf = 0; nf < 8; ++nf) {
            int col = n0 + wn * 64 + nf * 8 + t * 2;
            float2 bv = *(const float2*)&bias[col];
            float2 r0, r1;
            r0.x = c[mf][nf][0] + bv.x;
            r0.y = c[mf][nf][1] + bv.y;
            r1.x = c[mf][nf][2] + bv.x;
            r1.y = c[mf][nf][3] + bv.y;
            if (relu) {
                r0.x = fmaxf(r0.x, 0.f); r0.y = fmaxf(r0.y, 0.f);
                r1.x = fmaxf(r1.x, 0.f); r1.y = fmaxf(r1.y, 0.f);
            }
            *(float2*)&C[(size_t)row0 * N + col]       = r0;
            *(float2*)&C[(size_t)(row0 + 8) * N + col] = r1;
        }
    }
}

// ==============================================================================
// Mask kernel (fp32 exact)
// ==============================================================================
__global__ __launch_bounds__(256) void mask_kernel(
    const float* __restrict__ T1, const float* __restrict__ W2,
    const float* __restrict__ b2, const float* __restrict__ HS,
    float* __restrict__ maskOut)
{
    __shared__ float As[16][68];
    __shared__ float Ws[16][68];
    __shared__ float T2[64][68];
    __shared__ float HSs[16][68];
    __shared__ float Sc[64][16];

    const int tid = threadIdx.x;
    const int tx = tid & 15;
    const int ty = tid >> 4;
    const int m0 = blockIdx.x * 64;

    {
        int hrow = tid >> 4;
        int c4   = (tid & 15) * 4;
        float4 v = *(const float4*)&HS[(size_t)hrow * 64 + c4];
        *(float4*)&HSs[hrow][c4] = v;
    }

    float acc[4][4];
#pragma unroll
    for (int i = 0; i < 4; ++i)
#pragma unroll
        for (int j = 0; j < 4; ++j) acc[i][j] = 0.f;

    const int row = tid >> 2;
    const int kc  = (tid & 3) * 4;

    for (int kk = 0; kk < MLP_H; kk += 16) {
        float4 a = *(const float4*)&T1[(size_t)(m0 + row) * MLP_H + kk + kc];
        As[kc + 0][row] = a.x; As[kc + 1][row] = a.y;
        As[kc + 2][row] = a.z; As[kc + 3][row] = a.w;
        float4 w = *(const float4*)&W2[(size_t)row * MLP_H + kk + kc];
        Ws[kc + 0][row] = w.x; Ws[kc + 1][row] = w.y;
        Ws[kc + 2][row] = w.z; Ws[kc + 3][row] = w.w;
        __syncthreads();
#pragma unroll
        for (int k = 0; k < 16; ++k) {
            float a4[4], b4[4];
            *(float4*)&a4[0] = *(const float4*)&As[k][ty * 4];
            *(float4*)&b4[0] = *(const float4*)&Ws[k][tx * 4];
#pragma unroll
            for (int i = 0; i < 4; ++i)
#pragma unroll
                for (int j = 0; j < 4; ++j)
                    acc[i][j] = fmaf(a4[i], b4[j], acc[i][j]);
        }
        __syncthreads();
    }

#pragma unroll
    for (int i = 0; i < 4; ++i)
#pragma unroll
        for (int j = 0; j < 4; ++j)
            T2[ty * 4 + i][tx * 4 + j] = acc[i][j] + b2[tx * 4 + j];
    __syncthreads();

    {
        int r  = tid >> 2;
        int hg = (tid & 3) * 4;
        float sc[4] = {0.f, 0.f, 0.f, 0.f};
#pragma unroll 8
        for (int d = 0; d < 64; ++d) {
            float tv = T2[r][d];
            sc[0] = fmaf(tv, HSs[hg + 0][d], sc[0]);
            sc[1] = fmaf(tv, HSs[hg + 1][d], sc[1]);
            sc[2] = fmaf(tv, HSs[hg + 2][d], sc[2]);
            sc[3] = fmaf(tv, HSs[hg + 3][d], sc[3]);
        }
        *(float4*)&Sc[r][hg] = make_float4(sc[0], sc[1], sc[2], sc[3]);
    }
    __syncthreads();

    if (tid < 64) {
        float vals[16];
#pragma unroll
        for (int h = 0; h < 16; ++h) vals[h] = Sc[tid][h];
        bool used[16];
#pragma unroll
        for (int h = 0; h < 16; ++h) used[h] = false;
        float kth = -1e30f;
        for (int it = 0; it < KEEP; ++it) {
            float mx = -1e30f; int mi = 0;
            for (int h = 0; h < 16; ++h)
                if (!used[h] && vals[h] > mx) { mx = vals[h]; mi = h; }
            used[mi] = true;
            kth = mx;
        }
        for (int h = 0; h < 16; ++h)
            maskOut[(size_t)(m0 + tid) * HEADS + h] = (vals[h] >= kth) ? 1.f : 0.f;
    }
}

// ==============================================================================
// Flash attention v3: all fragment traffic via ldmatrix; P register-resident.
// QK^T: split fp16 3-term. P*V: fp16 P (register A-frags) x split fp16 V 2-term.
// K/V stored as fp16 rows (144B stride), double-buffered. ONE sync per k-tile.
// ==============================================================================
#define VHS 72                          // halves per K/V row (64 + 8 pad)
#define COMP_H (64 * VHS)               // halves per component per buffer (4608)
#define FLASH3_SMEM (8 * COMP_H * 2)    // Kh,Kl,Vh,Vl x 2 bufs x 2B = 73728
#define QSTG 68

__global__ __launch_bounds__(256, 1) void flash_mma_kernel(
    const float* __restrict__ Qg, const float* __restrict__ Kg,
    const float* __restrict__ Vg, const float* __restrict__ maskp,
    float* __restrict__ Og)
{
    extern __shared__ __align__(16) char smc[];
    __half* KH = (__half*)smc;              // [2][64][VHS]
    __half* KL = KH + 2 * COMP_H;
    __half* VH = KL + 2 * COMP_H;
    __half* VL = VH + 2 * COMP_H;
    const uint32_t base_u = smem_to_u32(smc);
    const uint32_t KH_u = base_u;
    const uint32_t KL_u = KH_u + 2 * COMP_H * 2;
    const uint32_t VH_u = KL_u + 2 * COMP_H * 2;
    const uint32_t VL_u = VH_u + 2 * COMP_H * 2;

    const int tid  = threadIdx.x;
    const int lane = tid & 31;
    const int wid  = tid >> 5;
    const int g    = lane >> 2;
    const int t    = lane & 3;
    const int mbase = wid * 16;

    const int qt = blockIdx.x;
    const int h  = blockIdx.y;
    const int b  = blockIdx.z;
    const int s0 = qt * 128;
    const size_t rowstride = (size_t)BATCH * EMB;
    const size_t cbase = (size_t)b * EMB + (size_t)h * HDIM;

    // ---- stage Q (reuses the K/V smem region before the pipeline starts) ----
    float* Qst = (float*)smc;
#pragma unroll
    for (int p = 0; p < 8; ++p) {
        int idx = tid + p * 256;
        int row = idx >> 4;
        int c4  = (idx & 15) * 4;
        float4 v = *(const float4*)&Qg[(size_t)(s0 + row) * rowstride + cbase + c4];
        *(float4*)&Qst[row * QSTG + c4] = v;
    }
    __syncthreads();

    // ---- Q fragments (split fp16 hi/lo), register resident ----
    uint32_t qh[4][4], ql[4][4];
#pragma unroll
    for (int ks = 0; ks < 4; ++ks) {
        int r0 = mbase + g, r1 = mbase + g + 8;
        int c0 = ks * 16 + 2 * t;
#pragma unroll
        for (int fi = 0; fi < 4; ++fi) {
            int rr = (fi & 1) ? r1 : r0;
            int cc = c0 + ((fi >> 1) ? 8 : 0);
            float f0 = Qst[rr * QSTG + cc];
            float f1 = Qst[rr * QSTG + cc + 1];
            __half h0 = __float2half_rn(f0);
            __half h1 = __float2half_rn(f1);
            qh[ks][fi] = pack_h2(h0, h1);
            ql[ks][fi] = pack_h2(__float2half_rn(f0 - __half2float(h0)),
                                 __float2half_rn(f1 - __half2float(h1)));
        }
    }
    __syncthreads();   // Q reads done; region now owned by K/V

    // ---- K/V loaders (global -> regs -> split fp16 smem) ----
    const int lrow = tid >> 4;           // 0..15
    const int lc4  = (tid & 15) * 4;
    float4 kr[4], vr[4];
    auto load_kv = [&](int kt) {
#pragma unroll
        for (int p = 0; p < 4; ++p) {
            int row = lrow + p * 16;
            size_t goff = (size_t)(kt * 64 + row) * rowstride + cbase + lc4;
            kr[p] = *(const float4*)&Kg[goff];
            vr[p] = *(const float4*)&Vg[goff];
        }
    };
    auto store_kv = [&](int bb) {
        const int boff = bb * COMP_H;
#pragma unroll
        for (int p = 0; p < 4; ++p) {
            int j = lrow + p * 16;
            int off = boff + j * VHS + lc4;
            uint2 hi, lo;
            split4(kr[p], hi, lo);
            *(uint2*)&KH[off] = hi;
            *(uint2*)&KL[off] = lo;
            split4(vr[p], hi, lo);
            *(uint2*)&VH[off] = hi;
            *(uint2*)&VL[off] = lo;
        }
    };

    load_kv(0);
    store_kv(0);
    __syncthreads();

    // ldmatrix per-lane offsets (in halves)
    const int k_r = (lane & 7) + ((lane >> 4) << 3);   // K (non-trans) row
    const int k_c = (lane & 8);                        // K col offset
    const int v_r = lane & 15;                         // V (trans) row
    const int v_c = (lane >> 4) << 3;                  // V col offset

    float o[8][4];
    float m0r = -1e30f, m1r = -1e30f, l0r = 0.f, l1r = 0.f;
#pragma unroll
    for (int nf = 0; nf < 8; ++nf)
#pragma unroll
        for (int i = 0; i < 4; ++i) o[nf][i] = 0.f;

    const int NKT = S_LEN / 64;
    for (int kt = 0; kt < NKT; ++kt) {
        const int bb = kt & 1;
        const uint32_t khb = KH_u + bb * COMP_H * 2;
        const uint32_t klb = KL_u + bb * COMP_H * 2;
        const uint32_t vhb = VH_u + bb * COMP_H * 2;
        const uint32_t vlb = VL_u + bb * COMP_H * 2;

        // ---- S = Q K^T (split fp16, 3-term); K frags via ldmatrix ----
        float sc[8][4];
#pragma unroll
        for (int nf = 0; nf < 8; ++nf)
#pragma unroll
            for (int i = 0; i < 4; ++i) sc[nf][i] = 0.f;

#pragma unroll
        for (int ks = 0; ks < 4; ++ks) {
#pragma unroll
            for (int jp = 0; jp < 4; ++jp) {         // key blocks of 16
                uint32_t off = (uint32_t)(((jp * 16 + k_r) * VHS + ks * 16 + k_c) * 2);
                uint32_t bh[4], bl[4];
                ldsm_x4(bh, khb + off);
                ldsm_x4(bl, klb + off);
                mma_f16(sc[2 * jp],     qh[ks], bh[0], bh[1]);
                mma_f16(sc[2 * jp],     ql[ks], bh[0], bh[1]);
                mma_f16(sc[2 * jp],     qh[ks], bl[0], bl[1]);
                mma_f16(sc[2 * jp + 1], qh[ks], bh[2], bh[3]);
                mma_f16(sc[2 * jp + 1], ql[ks], bh[2], bh[3]);
                mma_f16(sc[2 * jp + 1], qh[ks], bl[2], bl[3]);
            }
        }

        if (kt + 1 < NKT) load_kv(kt + 1);

        // ---- online softmax ----
        float tm0 = -1e30f, tm1 = -1e30f;
#pragma unroll
        for (int nf = 0; nf < 8; ++nf) {
            tm0 = fmaxf(tm0, fmaxf(sc[nf][0], sc[nf][1]));
            tm1 = fmaxf(tm1, fmaxf(sc[nf][2], sc[nf][3]));
        }
        tm0 = fmaxf(tm0, __shfl_xor_sync(0xffffffffu, tm0, 1));
        tm0 = fmaxf(tm0, __shfl_xor_sync(0xffffffffu, tm0, 2));
        tm1 = fmaxf(tm1, __shfl_xor_sync(0xffffffffu, tm1, 1));
        tm1 = fmaxf(tm1, __shfl_xor_sync(0xffffffffu, tm1, 2));

        float mn0 = fmaxf(m0r, tm0);
        float mn1 = fmaxf(m1r, tm1);
        float al0 = __expf(m0r - mn0);
        float al1 = __expf(m1r - mn1);

        float ls0 = 0.f, ls1 = 0.f;
#pragma unroll
        for (int nf = 0; nf < 8; ++nf) {
            sc[nf][0] = __expf(sc[nf][0] - mn0);
            sc[nf][1] = __expf(sc[nf][1] - mn0);
            sc[nf][2] = __expf(sc[nf][2] - mn1);
            sc[nf][3] = __expf(sc[nf][3] - mn1);
            ls0 += sc[nf][0] + sc[nf][1];
            ls1 += sc[nf][2] + sc[nf][3];
        }
        ls0 += __shfl_xor_sync(0xffffffffu, ls0, 1);
        ls0 += __shfl_xor_sync(0xffffffffu, ls0, 2);
        ls1 += __shfl_xor_sync(0xffffffffu, ls1, 1);
        ls1 += __shfl_xor_sync(0xffffffffu, ls1, 2);

        l0r = l0r * al0 + ls0;  m0r = mn0;
        l1r = l1r * al1 + ls1;  m1r = mn1;

#pragma unroll
        for (int nf = 0; nf < 8; ++nf) {
            o[nf][0] *= al0; o[nf][1] *= al0;
            o[nf][2] *= al1; o[nf][3] *= al1;
        }

        // ---- P A-fragments directly from S C-fragments (no smem) ----
        uint32_t pa[4][4];
#pragma unroll
        for (int ks = 0; ks < 4; ++ks) {
            pa[ks][0] = pack_f2h2(sc[2 * ks][0],     sc[2 * ks][1]);
            pa[ks][1] = pack_f2h2(sc[2 * ks][2],     sc[2 * ks][3]);
            pa[ks][2] = pack_f2h2(sc[2 * ks + 1][0], sc[2 * ks + 1][1]);
            pa[ks][3] = pack_f2h2(sc[2 * ks + 1][2], sc[2 * ks + 1][3]);
        }

        // ---- O += P V (fp16 P x split fp16 V); V frags via ldmatrix.trans ----
#pragma unroll
        for (int ks = 0; ks < 4; ++ks) {
#pragma unroll
            for (int dp = 0; dp < 4; ++dp) {         // d blocks of 16
                uint32_t off = (uint32_t)(((ks * 16 + v_r) * VHS + dp * 16 + v_c) * 2);
                uint32_t vh[4], vl[4];
                ldsm_x4_t(vh, vhb + off);
                ldsm_x4_t(vl, vlb + off);
                mma_f16(o[2 * dp],     pa[ks], vh[0], vh[1]);
                mma_f16(o[2 * dp],     pa[ks], vl[0], vl[1]);
                mma_f16(o[2 * dp + 1], pa[ks], vh[2], vh[3]);
                mma_f16(o[2 * dp + 1], pa[ks], vl[2], vl[3]);
            }
        }

        if (kt + 1 < NKT) store_kv(bb ^ 1);
        __syncthreads();
    }

    // ---- epilogue ----
    int srow0 = s0 + mbase + g;
    int srow1 = srow0 + 8;
    float mv0 = maskp[((size_t)srow0 * BATCH + b) * HEADS + h];
    float mv1 = maskp[((size_t)srow1 * BATCH + b) * HEADS + h];
    float inv0 = mv0 / l0r;
    float inv1 = mv1 / l1r;
#pragma unroll
    for (int nf = 0; nf < 8; ++nf) {
        int col = nf * 8 + 2 * t;
        float2 r0 = make_float2(o[nf][0] * inv0, o[nf][1] * inv0);
        float2 r1 = make_float2(o[nf][2] * inv1, o[nf][3] * inv1);
        *(float2*)&Og[(size_t)srow0 * rowstride + cbase + col] = r0;
        *(float2*)&Og[(size_t)srow1 * rowstride + cbase + col] = r1;
    }
}

// ==============================================================================
// launch
// ==============================================================================
extern "C" void kernel_launch(void* const* d_in, const int* in_sizes, int n_in,
                              void* d_out, int out_size)
{
    (void)in_sizes; (void)n_in; (void)out_size;
    const float* query   = (const float*)d_in[0];
    const float* q_w     = (const float*)d_in[1];
    const float* q_b     = (const float*)d_in[2];
    const float* k_w     = (const float*)d_in[3];
    const float* k_b     = (const float*)d_in[4];
    const float* v_w     = (const float*)d_in[5];
    const float* v_b     = (const float*)d_in[6];
    const float* out_w   = (const float*)d_in[7];
    const float* out_b   = (const float*)d_in[8];
    const float* inf1_w  = (const float*)d_in[9];
    const float* inf1_b  = (const float*)d_in[10];
    const float* inf2_w  = (const float*)d_in[11];
    const float* inf2_b  = (const float*)d_in[12];
    const float* head_sig= (const float*)d_in[13];
    float* out = (float*)d_out;

    float* pq;  cudaGetSymbolAddress((void**)&pq,  g_q);
    float* pk;  cudaGetSymbolAddress((void**)&pk,  g_k);
    float* pv;  cudaGetSymbolAddress((void**)&pv,  g_v);
    float* po;  cudaGetSymbolAddress((void**)&po,  g_o);
    float* pt1; cudaGetSymbolAddress((void**)&pt1, g_t1);
    float* pm;  cudaGetSymbolAddress((void**)&pm,  g_mask);

    cudaFuncSetAttribute(gemm_tf32_mma_kernel,
                         cudaFuncAttributeMaxDynamicSharedMemorySize, GEMM_MMA_SMEM);
    cudaFuncSetAttribute(gemm_f16split_kernel,
                         cudaFuncAttributeMaxDynamicSharedMemorySize, GEMM_F16S_SMEM);
    cudaFuncSetAttribute(flash_mma_kernel,
                         cudaFuncAttributeMaxDynamicSharedMemorySize, FLASH3_SMEM);

    const float scaling = 0.125f;   // 64^-0.5

    dim3 gT(EMB / WBN, MROWS / WBM);            // 8 x 32
    gemm_tf32_mma_kernel<<<gT, 256, GEMM_MMA_SMEM>>>(query, q_w, q_b, pq, MROWS, EMB, EMB, scaling);
    gemm_tf32_mma_kernel<<<gT, 256, GEMM_MMA_SMEM>>>(query, k_w, k_b, pk, MROWS, EMB, EMB, 1.f);
    gemm_tf32_mma_kernel<<<gT, 256, GEMM_MMA_SMEM>>>(query, v_w, v_b, pv, MROWS, EMB, EMB, 1.f);

    dim3 g1(MLP_H / WBN, MROWS / WBM);          // 4 x 32
    gemm_f16split_kernel<<<g1, 256, GEMM_F16S_SMEM>>>(query, inf1_w, inf1_b, pt1, MROWS, MLP_H, EMB, 1);
    mask_kernel<<<MROWS / 64, 256>>>(pt1, inf2_w, inf2_b, head_sig, pm);

    dim3 gf(S_LEN / 128, HEADS, BATCH);         // 16 x 16 x 2
    flash_mma_kernel<<<gf, 256, FLASH3_SMEM>>>(pq, pk, pv, pm, po);

    gemm_tf32_mma_kernel<<<gT, 256, GEMM_MMA_SMEM>>>(po, out_w, out_b, out, MROWS, EMB, EMB, 1.f);
}

// round 7
// speedup vs baseline: 3.1710x; 1.0290x over previous
#include <cuda_runtime.h>
#include <cuda_bf16.h>
#include <cuda_fp16.h>
#include <cstdint>
#include <cstddef>

// Problem constants
#define S_LEN 2048
#define BATCH 2
#define EMB   1024
#define HEADS 16
#define HDIM  64
#define MROWS (S_LEN * BATCH)      // 4096
#define MLP_H 512
#define SIGD  64
#define KEEP  12                   // NUM_HEADS - INACTIVE

// ---------------- scratch (device globals; no allocation allowed) -------------
__device__ float g_q[MROWS * EMB];
__device__ float g_k[MROWS * EMB];
__device__ float g_v[MROWS * EMB];
__device__ float g_o[MROWS * EMB];
__device__ float g_t1[MROWS * MLP_H];
__device__ float g_mask[MROWS * HEADS];

// ======================= warp-level mma.sync helpers ==========================
__device__ __forceinline__ void mma_tf32(float* c, const uint32_t* a,
                                         uint32_t b0, uint32_t b1)
{
    asm volatile(
        "mma.sync.aligned.m16n8k8.row.col.f32.tf32.tf32.f32 "
        "{%0,%1,%2,%3}, {%4,%5,%6,%7}, {%8,%9}, {%0,%1,%2,%3};"
        : "+f"(c[0]), "+f"(c[1]), "+f"(c[2]), "+f"(c[3])
        : "r"(a[0]), "r"(a[1]), "r"(a[2]), "r"(a[3]), "r"(b0), "r"(b1));
}

__device__ __forceinline__ void mma_f16(float* c, const uint32_t* a,
                                        uint32_t b0, uint32_t b1)
{
    asm volatile(
        "mma.sync.aligned.m16n8k16.row.col.f32.f16.f16.f32 "
        "{%0,%1,%2,%3}, {%4,%5,%6,%7}, {%8,%9}, {%0,%1,%2,%3};"
        : "+f"(c[0]), "+f"(c[1]), "+f"(c[2]), "+f"(c[3])
        : "r"(a[0]), "r"(a[1]), "r"(a[2]), "r"(a[3]), "r"(b0), "r"(b1));
}

__device__ __forceinline__ void ldsm_x4(uint32_t* r, uint32_t addr) {
    asm volatile(
        "ldmatrix.sync.aligned.m8n8.x4.shared.b16 {%0,%1,%2,%3}, [%4];"
        : "=r"(r[0]), "=r"(r[1]), "=r"(r[2]), "=r"(r[3]) : "r"(addr));
}
__device__ __forceinline__ void ldsm_x4_t(uint32_t* r, uint32_t addr) {
    asm volatile(
        "ldmatrix.sync.aligned.m8n8.x4.trans.shared.b16 {%0,%1,%2,%3}, [%4];"
        : "=r"(r[0]), "=r"(r[1]), "=r"(r[2]), "=r"(r[3]) : "r"(addr));
}

__device__ __forceinline__ uint32_t smem_to_u32(const void* smem_ptr) {
    uint32_t addr;
    asm("{ .reg .u64 tmp; cvta.to.shared.u64 tmp, %1; cvt.u32.u64 %0, tmp; }"
        : "=r"(addr) : "l"(smem_ptr));
    return addr;
}

__device__ __forceinline__ uint32_t f2tf32(float f) {
    uint32_t u;
    asm("cvt.rna.tf32.f32 %0, %1;" : "=r"(u) : "f"(f));
    return u;
}
__device__ __forceinline__ uint4 cvt_tf32x4(float4 v) {
    uint4 u;
    u.x = f2tf32(v.x); u.y = f2tf32(v.y);
    u.z = f2tf32(v.z); u.w = f2tf32(v.w);
    return u;
}
__device__ __forceinline__ uint32_t pack_h2(__half a, __half b) {
    __half2 h = __halves2half2(a, b);
    return *(uint32_t*)&h;
}
__device__ __forceinline__ uint32_t pack_f2h2(float a, float b) {
    return pack_h2(__float2half_rn(a), __float2half_rn(b));
}
__device__ __forceinline__ void split4(float4 v, uint2& hi, uint2& lo) {
    float f[4] = {v.x, v.y, v.z, v.w};
    __half hh[4], hl[4];
#pragma unroll
    for (int e = 0; e < 4; ++e) {
        hh[e] = __float2half_rn(f[e]);
        hl[e] = __float2half_rn(f[e] - __half2float(hh[e]));
    }
    hi = make_uint2(pack_h2(hh[0], hh[1]), pack_h2(hh[2], hh[3]));
    lo = make_uint2(pack_h2(hl[0], hl[1]), pack_h2(hl[2], hl[3]));
}

// ==============================================================================
// TF32 mma.sync GEMM body: C = (A @ W^T + bias) * scale
// 128x128x32 tile, 256 threads, SINGLE-buffered smem + register prefetch
// (measured best config; double-buffering regressed at this occupancy).
// ==============================================================================
#define WBM 128
#define WBN 128
#define WBK 32
#define ASTR 36
#define TILE_WORDS (128 * ASTR)
#define GEMM_MMA_SMEM (2 * TILE_WORDS * 4)      // A + B = 36864 B

__device__ __forceinline__ void gemm_tf32_body(
    const float* __restrict__ A, const float* __restrict__ W,
    const float* __restrict__ bias, float* __restrict__ C,
    int N, int K, float scale, int m0, int n0, uint32_t* smw)
{
    uint32_t* Asm = smw;
    uint32_t* Bsm = smw + TILE_WORDS;

    const int tid  = threadIdx.x;
    const int lane = tid & 31;
    const int wid  = tid >> 5;
    const int wm   = wid & 3;
    const int wn   = wid >> 2;
    const int g    = lane >> 2;
    const int t    = lane & 3;
    const int NB   = K / WBK;

    const int lrow = tid >> 3;
    const int lc4  = (tid & 7) * 4;

    float c[2][8][4];
#pragma unroll
    for (int mf = 0; mf < 2; ++mf)
#pragma unroll
        for (int nf = 0; nf < 8; ++nf)
#pragma unroll
            for (int i = 0; i < 4; ++i) c[mf][nf][i] = 0.f;

    float4 ra[4], rb[4];
    auto load_regs = [&](int kk) {
#pragma unroll
        for (int p = 0; p < 4; ++p) {
            int row = lrow + p * 32;
            ra[p] = *(const float4*)&A[(size_t)(m0 + row) * K + kk + lc4];
            rb[p] = *(const float4*)&W[(size_t)(n0 + row) * K + kk + lc4];
        }
    };
    auto store_smem = [&]() {
#pragma unroll
        for (int p = 0; p < 4; ++p) {
            int row = lrow + p * 32;
            *(uint4*)&Asm[row * ASTR + lc4] = cvt_tf32x4(ra[p]);
            *(uint4*)&Bsm[row * ASTR + lc4] = cvt_tf32x4(rb[p]);
        }
    };

    load_regs(0);
    store_smem();
    __syncthreads();

    for (int kb = 0; kb < NB; ++kb) {
        const bool pre = (kb + 1 < NB);
        if (pre) load_regs((kb + 1) * WBK);

#pragma unroll
        for (int ks = 0; ks < 4; ++ks) {
            uint32_t a[2][4];
#pragma unroll
            for (int mf = 0; mf < 2; ++mf) {
                int r  = wm * 32 + mf * 16 + g;
                int cc = ks * 8 + t;
                a[mf][0] = Asm[r * ASTR + cc];
                a[mf][1] = Asm[(r + 8) * ASTR + cc];
                a[mf][2] = Asm[r * ASTR + cc + 4];
                a[mf][3] = Asm[(r + 8) * ASTR + cc + 4];
            }
#pragma unroll
            for (int nf = 0; nf < 8; ++nf) {
                int r  = wn * 64 + nf * 8 + g;
                int cc = ks * 8 + t;
                uint32_t b0 = Bsm[r * ASTR + cc];
                uint32_t b1 = Bsm[r * ASTR + cc + 4];
                mma_tf32(c[0][nf], a[0], b0, b1);
                mma_tf32(c[1][nf], a[1], b0, b1);
            }
        }
        __syncthreads();
        if (pre) {
            store_smem();
            __syncthreads();
        }
    }

#pragma unroll
    for (int mf = 0; mf < 2; ++mf) {
        int row0 = m0 + wm * 32 + mf * 16 + g;
#pragma unroll
        for (int nf = 0; nf < 8; ++nf) {
            int col = n0 + wn * 64 + nf * 8 + t * 2;
            float2 bv = *(const float2*)&bias[col];
            float2 r0, r1;
            r0.x = (c[mf][nf][0] + bv.x) * scale;
            r0.y = (c[mf][nf][1] + bv.y) * scale;
            r1.x = (c[mf][nf][2] + bv.x) * scale;
            r1.y = (c[mf][nf][3] + bv.y) * scale;
            *(float2*)&C[(size_t)row0 * N + col]       = r0;
            *(float2*)&C[(size_t)(row0 + 8) * N + col] = r1;
        }
    }
}

__global__ __launch_bounds__(256, 2) void gemm_tf32_mma_kernel(
    const float* __restrict__ A, const float* __restrict__ W,
    const float* __restrict__ bias, float* __restrict__ C,
    int M, int N, int K, float scale)
{
    extern __shared__ uint32_t smw[];
    gemm_tf32_body(A, W, bias, C, N, K, scale,
                   blockIdx.y * WBM, blockIdx.x * WBN, smw);
}

// Fused q/k/v projection: one launch, 768 CTAs (better wave packing).
__global__ __launch_bounds__(256, 2) void qkv_fused_kernel(
    const float* __restrict__ A,
    const float* __restrict__ qw, const float* __restrict__ kw, const float* __restrict__ vw,
    const float* __restrict__ qb, const float* __restrict__ kb, const float* __restrict__ vb,
    float* __restrict__ oq, float* __restrict__ ok, float* __restrict__ ov,
    float qscale)
{
    extern __shared__ uint32_t smw[];
    const int sec = blockIdx.x >> 3;        // 0=q, 1=k, 2=v
    const int nx  = blockIdx.x & 7;
    const float* W  = (sec == 0) ? qw : (sec == 1) ? kw : vw;
    const float* Bv = (sec == 0) ? qb : (sec == 1) ? kb : vb;
    float* C        = (sec == 0) ? oq : (sec == 1) ? ok : ov;
    const float sc  = (sec == 0) ? qscale : 1.f;
    gemm_tf32_body(A, W, Bv, C, EMB, EMB, sc,
                   blockIdx.y * WBM, nx * WBN, smw);
}

// ==============================================================================
// Split-fp16 GEMM (near-fp32): C = relu?(A @ W^T + bias)
// Single-buffered (measured best), 41KB smem. Mask-path inf1.
// ==============================================================================
#define HSTR 20
#define HTILE (128 * HSTR)
#define GEMM_F16S_SMEM (4 * HTILE * 4)   // Ah,Al,Wh,Wl = 40960 B

__global__ __launch_bounds__(256, 2) void gemm_f16split_kernel(
    const float* __restrict__ A, const float* __restrict__ W,
    const float* __restrict__ bias, float* __restrict__ C,
    int M, int N, int K, int relu)
{
    extern __shared__ uint32_t smh[];
    uint32_t* Ah = smh;
    uint32_t* Al = smh + HTILE;
    uint32_t* Wh = smh + 2 * HTILE;
    uint32_t* Wl = smh + 3 * HTILE;

    const int tid  = threadIdx.x;
    const int lane = tid & 31;
    const int wid  = tid >> 5;
    const int wm   = wid & 3;
    const int wn   = wid >> 2;
    const int g    = lane >> 2;
    const int t    = lane & 3;
    const int m0   = blockIdx.y * WBM;
    const int n0   = blockIdx.x * WBN;
    const int NB   = K / WBK;

    const int lrow = tid >> 3;
    const int lc4  = (tid & 7) * 4;
    const int lpr  = (tid & 7) * 2;

    float c[2][8][4];
#pragma unroll
    for (int mf = 0; mf < 2; ++mf)
#pragma unroll
        for (int nf = 0; nf < 8; ++nf)
#pragma unroll
            for (int i = 0; i < 4; ++i) c[mf][nf][i] = 0.f;

    float4 ra[4], rb[4];
    auto load_regs = [&](int kk) {
#pragma unroll
        for (int p = 0; p < 4; ++p) {
            int row = lrow + p * 32;
            ra[p] = *(const float4*)&A[(size_t)(m0 + row) * K + kk + lc4];
            rb[p] = *(const float4*)&W[(size_t)(n0 + row) * K + kk + lc4];
        }
    };
    auto store_smem = [&]() {
#pragma unroll
        for (int p = 0; p < 4; ++p) {
            int row = lrow + p * 32;
            uint2 hi, lo;
            split4(ra[p], hi, lo);
            *(uint2*)&Ah[row * HSTR + lpr] = hi;
            *(uint2*)&Al[row * HSTR + lpr] = lo;
            split4(rb[p], hi, lo);
            *(uint2*)&Wh[row * HSTR + lpr] = hi;
            *(uint2*)&Wl[row * HSTR + lpr] = lo;
        }
    };

    load_regs(0);
    store_smem();
    __syncthreads();

    for (int kb = 0; kb < NB; ++kb) {
        const bool pre = (kb + 1 < NB);
        if (pre) load_regs((kb + 1) * WBK);

#pragma unroll
        for (int ks = 0; ks < 2; ++ks) {
            uint32_t ah[2][4], al[2][4];
#pragma unroll
            for (int mf = 0; mf < 2; ++mf) {
                int r  = wm * 32 + mf * 16 + g;
                int cc = ks * 8 + t;
                ah[mf][0] = Ah[r * HSTR + cc];
                ah[mf][1] = Ah[(r + 8) * HSTR + cc];
                ah[mf][2] = Ah[r * HSTR + cc + 4];
                ah[mf][3] = Ah[(r + 8) * HSTR + cc + 4];
                al[mf][0] = Al[r * HSTR + cc];
                al[mf][1] = Al[(r + 8) * HSTR + cc];
                al[mf][2] = Al[r * HSTR + cc + 4];
                al[mf][3] = Al[(r + 8) * HSTR + cc + 4];
            }
#pragma unroll
            for (int nf = 0; nf < 8; ++nf) {
                int r  = wn * 64 + nf * 8 + g;
                int cc = ks * 8 + t;
                uint32_t bh0 = Wh[r * HSTR + cc];
                uint32_t bh1 = Wh[r * HSTR + cc + 4];
                uint32_t bl0 = Wl[r * HSTR + cc];
                uint32_t bl1 = Wl[r * HSTR + cc + 4];
#pragma unroll
                for (int mf = 0; mf < 2; ++mf) {
                    mma_f16(c[mf][nf], ah[mf], bh0, bh1);
                    mma_f16(c[mf][nf], al[mf], bh0, bh1);
                    mma_f16(c[mf][nf], ah[mf], bl0, bl1);
                }
            }
        }
        __syncthreads();
        if (pre) {
            store_smem();
            __syncthreads();
        }
    }

#pragma unroll
    for (int mf = 0; mf < 2; ++mf) {
        int row0 = m0 + wm * 32 + mf * 16 + g;
#pragma unroll
        for (int nf = 0; nf < 8; ++nf) {
            int col = n0 + wn * 64 + nf * 8 + t * 2;
            float2 bv = *(const float2*)&bias[col];
            float2 r0, r1;
            r0.x = c[mf][nf][0] + bv.x;
            r0.y = c[mf][nf][1] + bv.y;
            r1.x = c[mf][nf][2] + bv.x;
            r1.y = c[mf][nf][3] + bv.y;
            if (relu) {
                r0.x = fmaxf(r0.x, 0.f); r0.y = fmaxf(r0.y, 0.f);
                r1.x = fmaxf(r1.x, 0.f); r1.y = fmaxf(r1.y, 0.f);
            }
            *(float2*)&C[(size_t)row0 * N + col]       = r0;
            *(float2*)&C[(size_t)(row0 + 8) * N + col] = r1;
        }
    }
}

// ==============================================================================
// Mask kernel (fp32 exact)
// ==============================================================================
__global__ __launch_bounds__(256) void mask_kernel(
    const float* __restrict__ T1, const float* __restrict__ W2,
    const float* __restrict__ b2, const float* __restrict__ HS,
    float* __restrict__ maskOut)
{
    __shared__ float As[16][68];
    __shared__ float Ws[16][68];
    __shared__ float T2[64][68];
    __shared__ float HSs[16][68];
    __shared__ float Sc[64][16];

    const int tid = threadIdx.x;
    const int tx = tid & 15;
    const int ty = tid >> 4;
    const int m0 = blockIdx.x * 64;

    {
        int hrow = tid >> 4;
        int c4   = (tid & 15) * 4;
        float4 v = *(const float4*)&HS[(size_t)hrow * 64 + c4];
        *(float4*)&HSs[hrow][c4] = v;
    }

    float acc[4][4];
#pragma unroll
    for (int i = 0; i < 4; ++i)
#pragma unroll
        for (int j = 0; j < 4; ++j) acc[i][j] = 0.f;

    const int row = tid >> 2;
    const int kc  = (tid & 3) * 4;

    for (int kk = 0; kk < MLP_H; kk += 16) {
        float4 a = *(const float4*)&T1[(size_t)(m0 + row) * MLP_H + kk + kc];
        As[kc + 0][row] = a.x; As[kc + 1][row] = a.y;
        As[kc + 2][row] = a.z; As[kc + 3][row] = a.w;
        float4 w = *(const float4*)&W2[(size_t)row * MLP_H + kk + kc];
        Ws[kc + 0][row] = w.x; Ws[kc + 1][row] = w.y;
        Ws[kc + 2][row] = w.z; Ws[kc + 3][row] = w.w;
        __syncthreads();
#pragma unroll
        for (int k = 0; k < 16; ++k) {
            float a4[4], b4[4];
            *(float4*)&a4[0] = *(const float4*)&As[k][ty * 4];
            *(float4*)&b4[0] = *(const float4*)&Ws[k][tx * 4];
#pragma unroll
            for (int i = 0; i < 4; ++i)
#pragma unroll
                for (int j = 0; j < 4; ++j)
                    acc[i][j] = fmaf(a4[i], b4[j], acc[i][j]);
        }
        __syncthreads();
    }

#pragma unroll
    for (int i = 0; i < 4; ++i)
#pragma unroll
        for (int j = 0; j < 4; ++j)
            T2[ty * 4 + i][tx * 4 + j] = acc[i][j] + b2[tx * 4 + j];
    __syncthreads();

    {
        int r  = tid >> 2;
        int hg = (tid & 3) * 4;
        float sc[4] = {0.f, 0.f, 0.f, 0.f};
#pragma unroll 8
        for (int d = 0; d < 64; ++d) {
            float tv = T2[r][d];
            sc[0] = fmaf(tv, HSs[hg + 0][d], sc[0]);
            sc[1] = fmaf(tv, HSs[hg + 1][d], sc[1]);
            sc[2] = fmaf(tv, HSs[hg + 2][d], sc[2]);
            sc[3] = fmaf(tv, HSs[hg + 3][d], sc[3]);
        }
        *(float4*)&Sc[r][hg] = make_float4(sc[0], sc[1], sc[2], sc[3]);
    }
    __syncthreads();

    if (tid < 64) {
        float vals[16];
#pragma unroll
        for (int h = 0; h < 16; ++h) vals[h] = Sc[tid][h];
        bool used[16];
#pragma unroll
        for (int h = 0; h < 16; ++h) used[h] = false;
        float kth = -1e30f;
        for (int it = 0; it < KEEP; ++it) {
            float mx = -1e30f; int mi = 0;
            for (int h = 0; h < 16; ++h)
                if (!used[h] && vals[h] > mx) { mx = vals[h]; mi = h; }
            used[mi] = true;
            kth = mx;
        }
        for (int h = 0; h < 16; ++h)
            maskOut[(size_t)(m0 + tid) * HEADS + h] = (vals[h] >= kth) ? 1.f : 0.f;
    }
}

// ==============================================================================
// Flash attention v3 (unchanged from R6): ldmatrix frags, P register-resident.
// ==============================================================================
#define VHS 72
#define COMP_H (64 * VHS)
#define FLASH3_SMEM (8 * COMP_H * 2)    // 73728 B
#define QSTG 68

__global__ __launch_bounds__(256, 1) void flash_mma_kernel(
    const float* __restrict__ Qg, const float* __restrict__ Kg,
    const float* __restrict__ Vg, const float* __restrict__ maskp,
    float* __restrict__ Og)
{
    extern __shared__ __align__(16) char smc[];
    __half* KH = (__half*)smc;
    __half* KL = KH + 2 * COMP_H;
    __half* VH = KL + 2 * COMP_H;
    __half* VL = VH + 2 * COMP_H;
    const uint32_t base_u = smem_to_u32(smc);
    const uint32_t KH_u = base_u;
    const uint32_t KL_u = KH_u + 2 * COMP_H * 2;
    const uint32_t VH_u = KL_u + 2 * COMP_H * 2;
    const uint32_t VL_u = VH_u + 2 * COMP_H * 2;

    const int tid  = threadIdx.x;
    const int lane = tid & 31;
    const int wid  = tid >> 5;
    const int g    = lane >> 2;
    const int t    = lane & 3;
    const int mbase = wid * 16;

    const int qt = blockIdx.x;
    const int h  = blockIdx.y;
    const int b  = blockIdx.z;
    const int s0 = qt * 128;
    const size_t rowstride = (size_t)BATCH * EMB;
    const size_t cbase = (size_t)b * EMB + (size_t)h * HDIM;

    float* Qst = (float*)smc;
#pragma unroll
    for (int p = 0; p < 8; ++p) {
        int idx = tid + p * 256;
        int row = idx >> 4;
        int c4  = (idx & 15) * 4;
        float4 v = *(const float4*)&Qg[(size_t)(s0 + row) * rowstride + cbase + c4];
        *(float4*)&Qst[row * QSTG + c4] = v;
    }
    __syncthreads();

    uint32_t qh[4][4], ql[4][4];
#pragma unroll
    for (int ks = 0; ks < 4; ++ks) {
        int r0 = mbase + g, r1 = mbase + g + 8;
        int c0 = ks * 16 + 2 * t;
#pragma unroll
        for (int fi = 0; fi < 4; ++fi) {
            int rr = (fi & 1) ? r1 : r0;
            int cc = c0 + ((fi >> 1) ? 8 : 0);
            float f0 = Qst[rr * QSTG + cc];
            float f1 = Qst[rr * QSTG + cc + 1];
            __half h0 = __float2half_rn(f0);
            __half h1 = __float2half_rn(f1);
            qh[ks][fi] = pack_h2(h0, h1);
            ql[ks][fi] = pack_h2(__float2half_rn(f0 - __half2float(h0)),
                                 __float2half_rn(f1 - __half2float(h1)));
        }
    }
    __syncthreads();

    const int lrow = tid >> 4;
    const int lc4  = (tid & 15) * 4;
    float4 kr[4], vr[4];
    auto load_kv = [&](int kt) {
#pragma unroll
        for (int p = 0; p < 4; ++p) {
            int row = lrow + p * 16;
            size_t goff = (size_t)(kt * 64 + row) * rowstride + cbase + lc4;
            kr[p] = *(const float4*)&Kg[goff];
            vr[p] = *(const float4*)&Vg[goff];
        }
    };
    auto store_kv = [&](int bb) {
        const int boff = bb * COMP_H;
#pragma unroll
        for (int p = 0; p < 4; ++p) {
            int j = lrow + p * 16;
            int off = boff + j * VHS + lc4;
            uint2 hi, lo;
            split4(kr[p], hi, lo);
            *(uint2*)&KH[off] = hi;
            *(uint2*)&KL[off] = lo;
            split4(vr[p], hi, lo);
            *(uint2*)&VH[off] = hi;
            *(uint2*)&VL[off] = lo;
        }
    };

    load_kv(0);
    store_kv(0);
    __syncthreads();

    const int k_r = (lane & 7) + ((lane >> 4) << 3);
    const int k_c = (lane & 8);
    const int v_r = lane & 15;
    const int v_c = (lane >> 4) << 3;

    float o[8][4];
    float m0r = -1e30f, m1r = -1e30f, l0r = 0.f, l1r = 0.f;
#pragma unroll
    for (int nf = 0; nf < 8; ++nf)
#pragma unroll
        for (int i = 0; i < 4; ++i) o[nf][i] = 0.f;

    const int NKT = S_LEN / 64;
    for (int kt = 0; kt < NKT; ++kt) {
        const int bb = kt & 1;
        const uint32_t khb = KH_u + bb * COMP_H * 2;
        const uint32_t klb = KL_u + bb * COMP_H * 2;
        const uint32_t vhb = VH_u + bb * COMP_H * 2;
        const uint32_t vlb = VL_u + bb * COMP_H * 2;

        float sc[8][4];
#pragma unroll
        for (int nf = 0; nf < 8; ++nf)
#pragma unroll
            for (int i = 0; i < 4; ++i) sc[nf][i] = 0.f;

#pragma unroll
        for (int ks = 0; ks < 4; ++ks) {
#pragma unroll
            for (int jp = 0; jp < 4; ++jp) {
                uint32_t off = (uint32_t)(((jp * 16 + k_r) * VHS + ks * 16 + k_c) * 2);
                uint32_t bh[4], bl[4];
                ldsm_x4(bh, khb + off);
                ldsm_x4(bl, klb + off);
                mma_f16(sc[2 * jp],     qh[ks], bh[0], bh[1]);
                mma_f16(sc[2 * jp],     ql[ks], bh[0], bh[1]);
                mma_f16(sc[2 * jp],     qh[ks], bl[0], bl[1]);
                mma_f16(sc[2 * jp + 1], qh[ks], bh[2], bh[3]);
                mma_f16(sc[2 * jp + 1], ql[ks], bh[2], bh[3]);
                mma_f16(sc[2 * jp + 1], qh[ks], bl[2], bl[3]);
            }
        }

        if (kt + 1 < NKT) load_kv(kt + 1);

        float tm0 = -1e30f, tm1 = -1e30f;
#pragma unroll
        for (int nf = 0; nf < 8; ++nf) {
            tm0 = fmaxf(tm0, fmaxf(sc[nf][0], sc[nf][1]));
            tm1 = fmaxf(tm1, fmaxf(sc[nf][2], sc[nf][3]));
        }
        tm0 = fmaxf(tm0, __shfl_xor_sync(0xffffffffu, tm0, 1));
        tm0 = fmaxf(tm0, __shfl_xor_sync(0xffffffffu, tm0, 2));
        tm1 = fmaxf(tm1, __shfl_xor_sync(0xffffffffu, tm1, 1));
        tm1 = fmaxf(tm1, __shfl_xor_sync(0xffffffffu, tm1, 2));

        float mn0 = fmaxf(m0r, tm0);
        float mn1 = fmaxf(m1r, tm1);
        float al0 = __expf(m0r - mn0);
        float al1 = __expf(m1r - mn1);

        float ls0 = 0.f, ls1 = 0.f;
#pragma unroll
        for (int nf = 0; nf < 8; ++nf) {
            sc[nf][0] = __expf(sc[nf][0] - mn0);
            sc[nf][1] = __expf(sc[nf][1] - mn0);
            sc[nf][2] = __expf(sc[nf][2] - mn1);
            sc[nf][3] = __expf(sc[nf][3] - mn1);
            ls0 += sc[nf][0] + sc[nf][1];
            ls1 += sc[nf][2] + sc[nf][3];
        }
        ls0 += __shfl_xor_sync(0xffffffffu, ls0, 1);
        ls0 += __shfl_xor_sync(0xffffffffu, ls0, 2);
        ls1 += __shfl_xor_sync(0xffffffffu, ls1, 1);
        ls1 += __shfl_xor_sync(0xffffffffu, ls1, 2);

        l0r = l0r * al0 + ls0;  m0r = mn0;
        l1r = l1r * al1 + ls1;  m1r = mn1;

#pragma unroll
        for (int nf = 0; nf < 8; ++nf) {
            o[nf][0] *= al0; o[nf][1] *= al0;
            o[nf][2] *= al1; o[nf][3] *= al1;
        }

        uint32_t pa[4][4];
#pragma unroll
        for (int ks = 0; ks < 4; ++ks) {
            pa[ks][0] = pack_f2h2(sc[2 * ks][0],     sc[2 * ks][1]);
            pa[ks][1] = pack_f2h2(sc[2 * ks][2],     sc[2 * ks][3]);
            pa[ks][2] = pack_f2h2(sc[2 * ks + 1][0], sc[2 * ks + 1][1]);
            pa[ks][3] = pack_f2h2(sc[2 * ks + 1][2], sc[2 * ks + 1][3]);
        }

#pragma unroll
        for (int ks = 0; ks < 4; ++ks) {
#pragma unroll
            for (int dp = 0; dp < 4; ++dp) {
                uint32_t off = (uint32_t)(((ks * 16 + v_r) * VHS + dp * 16 + v_c) * 2);
                uint32_t vh[4], vl[4];
                ldsm_x4_t(vh, vhb + off);
                ldsm_x4_t(vl, vlb + off);
                mma_f16(o[2 * dp],     pa[ks], vh[0], vh[1]);
                mma_f16(o[2 * dp],     pa[ks], vl[0], vl[1]);
                mma_f16(o[2 * dp + 1], pa[ks], vh[2], vh[3]);
                mma_f16(o[2 * dp + 1], pa[ks], vl[2], vl[3]);
            }
        }

        if (kt + 1 < NKT) store_kv(bb ^ 1);
        __syncthreads();
    }

    int srow0 = s0 + mbase + g;
    int srow1 = srow0 + 8;
    float mv0 = maskp[((size_t)srow0 * BATCH + b) * HEADS + h];
    float mv1 = maskp[((size_t)srow1 * BATCH + b) * HEADS + h];
    float inv0 = mv0 / l0r;
    float inv1 = mv1 / l1r;
#pragma unroll
    for (int nf = 0; nf < 8; ++nf) {
        int col = nf * 8 + 2 * t;
        float2 r0 = make_float2(o[nf][0] * inv0, o[nf][1] * inv0);
        float2 r1 = make_float2(o[nf][2] * inv1, o[nf][3] * inv1);
        *(float2*)&Og[(size_t)srow0 * rowstride + cbase + col] = r0;
        *(float2*)&Og[(size_t)srow1 * rowstride + cbase + col] = r1;
    }
}

// ==============================================================================
// launch: fork-join — mask path (inf1 + mask) overlaps the fused qkv GEMM.
// Streams/events created once on the first (uncaptured) correctness call;
// during capture only record/wait nodes are added. Sequential fallback if
// creation failed.
// ==============================================================================
extern "C" void kernel_launch(void* const* d_in, const int* in_sizes, int n_in,
                              void* d_out, int out_size)
{
    (void)in_sizes; (void)n_in; (void)out_size;
    const float* query   = (const float*)d_in[0];
    const float* q_w     = (const float*)d_in[1];
    const float* q_b     = (const float*)d_in[2];
    const float* k_w     = (const float*)d_in[3];
    const float* k_b     = (const float*)d_in[4];
    const float* v_w     = (const float*)d_in[5];
    const float* v_b     = (const float*)d_in[6];
    const float* out_w   = (const float*)d_in[7];
    const float* out_b   = (const float*)d_in[8];
    const float* inf1_w  = (const float*)d_in[9];
    const float* inf1_b  = (const float*)d_in[10];
    const float* inf2_w  = (const float*)d_in[11];
    const float* inf2_b  = (const float*)d_in[12];
    const float* head_sig= (const float*)d_in[13];
    float* out = (float*)d_out;

    float* pq;  cudaGetSymbolAddress((void**)&pq,  g_q);
    float* pk;  cudaGetSymbolAddress((void**)&pk,  g_k);
    float* pv;  cudaGetSymbolAddress((void**)&pv,  g_v);
    float* po;  cudaGetSymbolAddress((void**)&po,  g_o);
    float* pt1; cudaGetSymbolAddress((void**)&pt1, g_t1);
    float* pm;  cudaGetSymbolAddress((void**)&pm,  g_mask);

    cudaFuncSetAttribute(gemm_tf32_mma_kernel,
                         cudaFuncAttributeMaxDynamicSharedMemorySize, GEMM_MMA_SMEM);
    cudaFuncSetAttribute(qkv_fused_kernel,
                         cudaFuncAttributeMaxDynamicSharedMemorySize, GEMM_MMA_SMEM);
    cudaFuncSetAttribute(gemm_f16split_kernel,
                         cudaFuncAttributeMaxDynamicSharedMemorySize, GEMM_F16S_SMEM);
    cudaFuncSetAttribute(flash_mma_kernel,
                         cudaFuncAttributeMaxDynamicSharedMemorySize, FLASH3_SMEM);

    // one-time side-stream setup (happens on the uncaptured correctness call)
    static cudaStream_t sB = nullptr;
    static cudaEvent_t  evF = nullptr, evJ = nullptr;
    static bool tried = false, okStreams = false;
    if (!tried) {
        tried = true;
        okStreams =
            (cudaStreamCreateWithFlags(&sB, cudaStreamNonBlocking) == cudaSuccess) &&
            (cudaEventCreateWithFlags(&evF, cudaEventDisableTiming) == cudaSuccess) &&
            (cudaEventCreateWithFlags(&evJ, cudaEventDisableTiming) == cudaSuccess);
    }

    const float scaling = 0.125f;   // 64^-0.5
    dim3 g1(MLP_H / WBN, MROWS / WBM);          // 4 x 32
    dim3 gQ(24, MROWS / WBM);                   // fused qkv: 768 CTAs
    dim3 gT(EMB / WBN, MROWS / WBM);            // 8 x 32
    dim3 gf(S_LEN / 128, HEADS, BATCH);         // 16 x 16 x 2

    if (okStreams) {
        // fork: mask path on side stream, concurrent with qkv
        cudaEventRecord(evF, (cudaStream_t)0);
        cudaStreamWaitEvent(sB, evF, 0);
        gemm_f16split_kernel<<<g1, 256, GEMM_F16S_SMEM, sB>>>(
            query, inf1_w, inf1_b, pt1, MROWS, MLP_H, EMB, 1);
        mask_kernel<<<MROWS / 64, 256, 0, sB>>>(pt1, inf2_w, inf2_b, head_sig, pm);
        cudaEventRecord(evJ, sB);

        qkv_fused_kernel<<<gQ, 256, GEMM_MMA_SMEM>>>(
            query, q_w, k_w, v_w, q_b, k_b, v_b, pq, pk, pv, scaling);

        // join before flash (needs q,k,v AND mask)
        cudaStreamWaitEvent((cudaStream_t)0, evJ, 0);
    } else {
        qkv_fused_kernel<<<gQ, 256, GEMM_MMA_SMEM>>>(
            query, q_w, k_w, v_w, q_b, k_b, v_b, pq, pk, pv, scaling);
        gemm_f16split_kernel<<<g1, 256, GEMM_F16S_SMEM>>>(
            query, inf1_w, inf1_b, pt1, MROWS, MLP_H, EMB, 1);
        mask_kernel<<<MROWS / 64, 256>>>(pt1, inf2_w, inf2_b, head_sig, pm);
    }

    flash_mma_kernel<<<gf, 256, FLASH3_SMEM>>>(pq, pk, pv, pm, po);

    gemm_tf32_mma_kernel<<<gT, 256, GEMM_MMA_SMEM>>>(po, out_w, out_b, out, MROWS, EMB, EMB, 1.f);
}